// round 13
// baseline (speedup 1.0000x reference)
#include <cuda_runtime.h>
#include <cuda_bf16.h>
#include <mma.h>
#include <cstdint>

using namespace nvcuda;

#define NB 32
#define NC 128
#define HW 4096
#define NROW (NB*NC)
#define KSPLIT 16

#define LDA 136   // padded ld for 128-wide bf16 rows (272B -> conflict-free)
#define LDW 24    // padded ld for 16-wide bf16 k-chunks
#define LDK 40    // padded ld for 32-wide bf16 k-chunks (80B rows)

// Scratch (device globals: allocation-free kernel_launch)
__device__ __align__(16) __nv_bfloat16 g_xh[NB*NC*HW], g_xl[NB*NC*HW];   // x pair
__device__ __align__(16) __nv_bfloat16 g_Eh[NB*NC*HW], g_El[NB*NC*HW];   // exp(B)
__device__ __align__(16) __nv_bfloat16 g_Fh[NB*NC*HW], g_Fl[NB*NC*HW];   // exp(V)
__device__ float g_gdp[KSPLIT*NB*NC*NC];          // partials of M = E @ x^T
__device__ __align__(16) __nv_bfloat16 g_gTh[NB*NC*NC];   // gd'^T [b][j][i]
__device__ __align__(16) __nv_bfloat16 g_gTl[NB*NC*NC];
__device__ float g_zBp[32*NROW], g_zVp[32*NROW];  // per-nblock partial exp sums
__device__ __align__(16) __nv_bfloat16 g_wh[2*NC*NC], g_wl[2*NC*NC];  // wB, wV pairs

__device__ __forceinline__ void split_bf16(float f, __nv_bfloat16& h, __nv_bfloat16& l) {
    h = __float2bfloat16(f);
    l = __float2bfloat16(f - __bfloat162float(h));
}
__device__ __forceinline__ void cp16(uint32_t saddr, const void* g) {
    asm volatile("cp.async.ca.shared.global [%0], [%1], 16;" :: "r"(saddr), "l"(g));
}
__device__ __forceinline__ uint32_t smem_u32(const void* p) {
    uint32_t a;
    asm("{ .reg .u64 t; cvta.to.shared.u64 t, %1; cvt.u32.u64 %0, t; }" : "=r"(a) : "l"(p));
    return a;
}

// ---------------------------------------------------------------------------
// Kernel W: wB, wV -> bf16 hi/lo (wA stays fp32; used exactly in gdgemm)
// ---------------------------------------------------------------------------
__global__ __launch_bounds__(256) void wconv_kernel(
    const float* __restrict__ wB, const float* __restrict__ wV)
{
    const float* ws[2] = {wB, wV};
    const int m = blockIdx.x;
    const float* w = ws[m];
    for (int idx = threadIdx.x; idx < NC*NC; idx += 256) {
        __nv_bfloat16 h, l;
        split_bf16(w[idx], h, l);
        g_wh[m*NC*NC + idx] = h;
        g_wl[m*NC*NC + idx] = l;
    }
}

// ---------------------------------------------------------------------------
// Kernel X: x fp32 -> bf16 hi/lo pair (one-time)
// ---------------------------------------------------------------------------
__global__ __launch_bounds__(256) void xconv_kernel(const float* __restrict__ x)
{
    const size_t i0 = ((size_t)blockIdx.x * 256 + threadIdx.x) * 4;
    float4 v = *(const float4*)(x + i0);
    __nv_bfloat16 h0, l0, h1, l1, h2, l2, h3, l3;
    split_bf16(v.x, h0, l0);
    split_bf16(v.y, h1, l1);
    split_bf16(v.z, h2, l2);
    split_bf16(v.w, h3, l3);
    *(__nv_bfloat162*)&g_xh[i0]     = __halves2bfloat162(h0, h1);
    *(__nv_bfloat162*)&g_xh[i0 + 2] = __halves2bfloat162(h2, h3);
    *(__nv_bfloat162*)&g_xl[i0]     = __halves2bfloat162(l0, l1);
    *(__nv_bfloat162*)&g_xl[i0 + 2] = __halves2bfloat162(l2, l3);
}

// ---------------------------------------------------------------------------
// Kernel P: E/F projections (m = blockIdx.z: 0 -> exp(wB x), 1 -> exp(wV x)).
// 3-term split (2-term failed precision: R12 rel_err 1.33e-3).
// W(pair) + X(pair) streamed as k=32 chunks via cp.async 2-stage pipeline.
// Epilogue staging + z-reduce ALIAS the pipeline buffers (dead after mainloop)
// -> smem 75.8 KB -> 3 blocks/SM. grid (32, 32, 2), 256 thr.
// stage (elems): [Wh 128*LDK][Wl 128*LDK][Xh 32*LDA][Xl 32*LDA]
// ---------------------------------------------------------------------------
#define P_STAGE (2*128*LDK + 2*32*LDA)
#define PROJ_SMEM (2*P_STAGE*2)

__global__ __launch_bounds__(256, 3) void proj_wmma()
{
    extern __shared__ char smraw[];
    __nv_bfloat16* sbase = (__nv_bfloat16*)smraw;
    const uint32_t sb_u32 = smem_u32(smraw);
    float* stage = (float*)smraw;                     // ALIAS buf0: 8 warps x 16x20
    float* zsm   = stage + 8*16*20;                   // ALIAS buf0 + 10240B: [128][4]

    const int tid = threadIdx.x, w = tid >> 5, lane = tid & 31;
    const int b = blockIdx.y, n0 = blockIdx.x * 128;
    const int m = blockIdx.z;
    const int wm = w & 3, wn = w >> 2;

    // staging maps (R10 map: W 4 segs/thread across hi|lo halves, X 4 segs)
    const int whl = tid >> 7, wr = tid & 127;
    const int xq0 = (tid & 127) * 4;
    const __nv_bfloat16* xsrc = (whl ? g_xl : g_xh);
    const __nv_bfloat16* wsrc0 = (whl ? g_wl : g_wh) + m*NC*NC + wr*NC;

    auto stage_cp = [&](int st, int kt) {
        const uint32_t sb = sb_u32 + st * P_STAGE * 2;
        const __nv_bfloat16* wsrc = wsrc0 + kt*32;
        const uint32_t wdst = sb + (whl*128*LDK + wr*LDK)*2;
        #pragma unroll
        for (int sg = 0; sg < 4; sg++)
            cp16(wdst + sg*16, wsrc + sg*8);
        const uint32_t xdst = sb + (2*128*LDK + whl*32*LDA)*2;
        #pragma unroll
        for (int q = 0; q < 4; q++) {
            const int idx = xq0 + q, row = idx >> 4, sg = idx & 15;
            cp16(xdst + (row*LDA + sg*8)*2,
                 xsrc + ((size_t)(b*NC + kt*32 + row))*HW + n0 + sg*8);
        }
        asm volatile("cp.async.commit_group;");
    };

    stage_cp(0, 0);
    stage_cp(1, 1);

    wmma::fragment<wmma::accumulator, 16, 16, 16, float> acc[2][4];
    #pragma unroll
    for (int mt = 0; mt < 2; mt++)
        #pragma unroll
        for (int nt = 0; nt < 4; nt++)
            wmma::fill_fragment(acc[mt][nt], 0.0f);

    #pragma unroll
    for (int kt = 0; kt < 4; kt++) {
        const int cur = kt & 1;
        if (kt == 3) asm volatile("cp.async.wait_group 0;" ::: "memory");
        else         asm volatile("cp.async.wait_group 1;" ::: "memory");
        __syncthreads();

        __nv_bfloat16* sWh = sbase + cur*P_STAGE;
        __nv_bfloat16* sWl = sWh + 128*LDK;
        __nv_bfloat16* sXh = sWl + 128*LDK;
        __nv_bfloat16* sXl = sXh + 32*LDA;

        #pragma unroll
        for (int kk = 0; kk < 2; kk++) {
            wmma::fragment<wmma::matrix_a, 16, 16, 16, __nv_bfloat16, wmma::row_major> ah[2], al[2];
            #pragma unroll
            for (int mt = 0; mt < 2; mt++) {
                const int o0 = wm*32 + mt*16;
                wmma::load_matrix_sync(ah[mt], &sWh[o0*LDK + kk*16], LDK);
                wmma::load_matrix_sync(al[mt], &sWl[o0*LDK + kk*16], LDK);
            }
            #pragma unroll
            for (int nt = 0; nt < 4; nt++) {
                wmma::fragment<wmma::matrix_b, 16, 16, 16, __nv_bfloat16, wmma::row_major> bh, bl;
                const int c0 = wn*64 + nt*16;
                wmma::load_matrix_sync(bh, &sXh[kk*16*LDA + c0], LDA);
                wmma::load_matrix_sync(bl, &sXl[kk*16*LDA + c0], LDA);
                #pragma unroll
                for (int mt = 0; mt < 2; mt++) {
                    wmma::mma_sync(acc[mt][nt], ah[mt], bh, acc[mt][nt]);
                    wmma::mma_sync(acc[mt][nt], ah[mt], bl, acc[mt][nt]);
                    wmma::mma_sync(acc[mt][nt], al[mt], bh, acc[mt][nt]);
                }
            }
        }

        __syncthreads();
        if (kt < 2) stage_cp(cur, kt + 2);
    }
    // NOTE: mainloop done; pipeline buffers now dead -> epilogue aliases buf0.
    __syncthreads();

    // Epilogue: exp, split, store pair + row partial sums
    float* st = stage + w * 16 * 20;
    float rs0 = 0.f, rs1 = 0.f;
    __nv_bfloat16* dh = (m == 0) ? g_Eh : g_Fh;
    __nv_bfloat16* dl = (m == 0) ? g_El : g_Fl;
    #pragma unroll
    for (int mt = 0; mt < 2; mt++)
        #pragma unroll
        for (int nt = 0; nt < 4; nt++) {
            wmma::store_matrix_sync(st, acc[mt][nt], 20, wmma::mem_row_major);
            __syncwarp();
            const int r = lane & 15, c8 = (lane >> 4) * 8;
            const int o = wm*32 + mt*16 + r;
            const int nn = n0 + wn*64 + nt*16 + c8;
            const float* sp = st + r*20 + c8;
            const size_t gb = ((size_t)b * NC + o) * HW + nn;
            float v[8];
            float lsum = 0.f;
            #pragma unroll
            for (int k = 0; k < 8; k++) { v[k] = __expf(sp[k]); lsum += v[k]; }
            if (mt == 0) rs0 += lsum; else rs1 += lsum;
            #pragma unroll
            for (int k = 0; k < 8; k += 2) {
                __nv_bfloat16 h0, l0, h1, l1;
                split_bf16(v[k],   h0, l0);
                split_bf16(v[k+1], h1, l1);
                *(__nv_bfloat162*)&dh[gb + k] = __halves2bfloat162(h0, h1);
                *(__nv_bfloat162*)&dl[gb + k] = __halves2bfloat162(l0, l1);
            }
            __syncwarp();
        }

    {
        const int idx = wn*2 + (lane >> 4), r = lane & 15;
        zsm[(wm*32 + r)*4 + idx]      = rs0;
        zsm[(wm*32 + 16 + r)*4 + idx] = rs1;
        __syncthreads();
        if (tid < 128) {
            float z = zsm[tid*4] + zsm[tid*4+1] + zsm[tid*4+2] + zsm[tid*4+3];
            float* zp = (m == 0) ? g_zBp : g_zVp;
            zp[blockIdx.x*NROW + b*NC + tid] = z;
        }
    }
}

// ---------------------------------------------------------------------------
// Kernel G: M partials: gdp[s][b][i][c] = sum_{n in 256-chunk} E[i,n]*x[c,n]
// block 128i x 64c (ch via blockIdx.z), warp 32x32, 256 thr, 3 blk/SM.
// cp.async 2-stage pipeline, k-chunk 32.  (3-term split)
// ---------------------------------------------------------------------------
#define GD_STAGE (2*128*LDK + 2*64*LDK)
#define GD_SMEM  (2*GD_STAGE*2)

__global__ __launch_bounds__(256, 3) void gd_wmma()
{
    extern __shared__ char smraw[];
    __nv_bfloat16* sbase = (__nv_bfloat16*)smraw;
    const uint32_t sb_u32 = smem_u32(smraw);

    const int tid = threadIdx.x, w = tid >> 5;
    const int s = blockIdx.x, b = blockIdx.y, jh = blockIdx.z;
    const int kbase = s * 256;
    const int wi = w & 3, wj = w >> 2;

    const int er = tid >> 1;
    const int es = (tid & 1) * 2;
    const int ar = tid >> 2, as_ = tid & 3;

    const __nv_bfloat16* Ehp = g_Eh + (size_t)(b*NC + er) * HW;
    const __nv_bfloat16* Elp = g_El + (size_t)(b*NC + er) * HW;
    const __nv_bfloat16* Ahp = g_xh + (size_t)(b*NC + jh*64 + ar) * HW;
    const __nv_bfloat16* Alp = g_xl + (size_t)(b*NC + jh*64 + ar) * HW;

    auto stage = [&](int st, int kt) {
        const int kk0 = kbase + kt * 32;
        const uint32_t sb = sb_u32 + st * GD_STAGE * 2;
        #pragma unroll
        for (int q = 0; q < 2; q++) {
            const int sg = es + q;
            cp16(sb + (er*LDK + sg*8)*2,           Ehp + kk0 + sg*8);
            cp16(sb + (128*LDK + er*LDK + sg*8)*2, Elp + kk0 + sg*8);
        }
        cp16(sb + (2*128*LDK + ar*LDK + as_*8)*2,          Ahp + kk0 + as_*8);
        cp16(sb + (2*128*LDK + 64*LDK + ar*LDK + as_*8)*2, Alp + kk0 + as_*8);
        asm volatile("cp.async.commit_group;");
    };

    stage(0, 0);
    stage(1, 1);

    wmma::fragment<wmma::accumulator, 16, 16, 16, float> acc[2][2];
    #pragma unroll
    for (int mt = 0; mt < 2; mt++)
        #pragma unroll
        for (int nt = 0; nt < 2; nt++)
            wmma::fill_fragment(acc[mt][nt], 0.0f);

    #pragma unroll
    for (int kt = 0; kt < 8; kt++) {
        const int cur = kt & 1;
        if (kt == 7) asm volatile("cp.async.wait_group 0;" ::: "memory");
        else         asm volatile("cp.async.wait_group 1;" ::: "memory");
        __syncthreads();

        __nv_bfloat16* sEh = sbase + cur*GD_STAGE;
        __nv_bfloat16* sEl = sEh + 128*LDK;
        __nv_bfloat16* sAh = sEl + 128*LDK;
        __nv_bfloat16* sAl = sAh + 64*LDK;

        #pragma unroll
        for (int kk = 0; kk < 2; kk++) {
            wmma::fragment<wmma::matrix_a, 16, 16, 16, __nv_bfloat16, wmma::row_major> ah[2], al[2];
            #pragma unroll
            for (int mt = 0; mt < 2; mt++) {
                const int i0 = wi*32 + mt*16;
                wmma::load_matrix_sync(ah[mt], &sEh[i0*LDK + kk*16], LDK);
                wmma::load_matrix_sync(al[mt], &sEl[i0*LDK + kk*16], LDK);
            }
            #pragma unroll
            for (int nt = 0; nt < 2; nt++) {
                wmma::fragment<wmma::matrix_b, 16, 16, 16, __nv_bfloat16, wmma::col_major> bh, bl;
                const int j0 = wj*32 + nt*16;
                wmma::load_matrix_sync(bh, &sAh[j0*LDK + kk*16], LDK);
                wmma::load_matrix_sync(bl, &sAl[j0*LDK + kk*16], LDK);
                #pragma unroll
                for (int mt = 0; mt < 2; mt++) {
                    wmma::mma_sync(acc[mt][nt], ah[mt], bh, acc[mt][nt]);
                    wmma::mma_sync(acc[mt][nt], ah[mt], bl, acc[mt][nt]);
                    wmma::mma_sync(acc[mt][nt], al[mt], bh, acc[mt][nt]);
                }
            }
        }

        __syncthreads();
        if (kt < 6) stage(cur, kt + 2);
    }

    float* gp = g_gdp + ((size_t)s * NB + b) * NC * NC;
    #pragma unroll
    for (int mt = 0; mt < 2; mt++)
        #pragma unroll
        for (int nt = 0; nt < 2; nt++)
            wmma::store_matrix_sync(gp + (wi*32 + mt*16) * NC + jh*64 + wj*32 + nt*16,
                                    acc[mt][nt], NC, wmma::mem_row_major);
}

// ---------------------------------------------------------------------------
// Kernel S2 (FUSED): per-b block computes
//   scl/bscl rows (from z-partials), M = sum_s gdp[s], then
//   gd'^T[b][j][i] = (sum_c M[i][c]*wA[j][c])*scl[i] + bA[j]*bscl[i]
// Exact fp32. grid 32 blocks, 256 threads (16x16), 8jx8i microtile.
// ---------------------------------------------------------------------------
#define LDR 132
#define GG_SMEM (2*128*LDR*4 + 2*128*4)

__global__ __launch_bounds__(256, 1) void gdgemm_kernel(
    const float* __restrict__ wA, const float* __restrict__ bA)
{
    extern __shared__ char smraw[];
    float* sM = (float*)smraw;          // [c][i]
    float* sW = sM + 128*LDR;           // [c][j]
    float* sscl  = sW + 128*LDR;        // [128]
    float* sbscl = sscl + 128;          // [128]

    const int b = blockIdx.x, tid = threadIdx.x;
    const int tx = tid & 15, ty = tid >> 4;

    // per-row scales from z partials (fused zfin)
    if (tid < 128) {
        const int row = b * NC + tid;
        float zb = 0.f, zv = 0.f;
        #pragma unroll
        for (int nb = 0; nb < 32; nb++) {
            zb += g_zBp[nb*NROW + row];
            zv += g_zVp[nb*NROW + row];
        }
        sscl[tid]  = 1.0f / (zb * (float)HW * zv);
        sbscl[tid] = 1.0f / ((float)HW * zv);
    }

    // M = sum over splits (fused gdsum), transposed into [c][i]; wA into [c][j]
    for (int idx = tid; idx < NC*NC; idx += 256) {
        const int r = idx >> 7, c = idx & 127;
        float sum = 0.f;
        #pragma unroll
        for (int s = 0; s < KSPLIT; s++)
            sum += g_gdp[(size_t)s * (NB*NC*NC) + b*NC*NC + idx];
        sM[c*LDR + r] = sum;
        sW[c*LDR + r] = wA[idx];
    }
    __syncthreads();

    float acc[8][8];
    #pragma unroll
    for (int a = 0; a < 8; a++)
        #pragma unroll
        for (int d = 0; d < 8; d++) acc[a][d] = 0.f;

    for (int c = 0; c < 128; c++) {
        float4 j0 = *(const float4*)&sW[c*LDR + ty*8];
        float4 j1 = *(const float4*)&sW[c*LDR + ty*8 + 4];
        float4 i0 = *(const float4*)&sM[c*LDR + tx*8];
        float4 i1 = *(const float4*)&sM[c*LDR + tx*8 + 4];
        const float jv[8] = {j0.x, j0.y, j0.z, j0.w, j1.x, j1.y, j1.z, j1.w};
        const float iv[8] = {i0.x, i0.y, i0.z, i0.w, i1.x, i1.y, i1.z, i1.w};
        #pragma unroll
        for (int a = 0; a < 8; a++)
            #pragma unroll
            for (int d = 0; d < 8; d++)
                acc[a][d] += jv[a] * iv[d];
    }

    #pragma unroll
    for (int a = 0; a < 8; a++) {
        const int j = ty*8 + a;
        const float bAj = bA[j];
        #pragma unroll
        for (int d = 0; d < 8; d += 2) {
            const int i = tx*8 + d;
            const float v0 = acc[a][d]   * sscl[i]   + bAj * sbscl[i];
            const float v1 = acc[a][d+1] * sscl[i+1] + bAj * sbscl[i+1];
            __nv_bfloat16 h0, l0, h1, l1;
            split_bf16(v0, h0, l0);
            split_bf16(v1, h1, l1);
            const size_t t = (size_t)b*NC*NC + (size_t)j*NC + i;
            *(__nv_bfloat162*)&g_gTh[t] = __halves2bfloat162(h0, h1);
            *(__nv_bfloat162*)&g_gTl[t] = __halves2bfloat162(l0, l1);
        }
    }
}

// ---------------------------------------------------------------------------
// Kernel O: out[b,j,n] = sum_i F[i,n]*gd'[i,j]  (3-term bf16 GEMM, K=128)
// cp.async 2-stage, k-chunk 16. grid (HW/128, NB), 256 thr, block 128j x 128n.
// ---------------------------------------------------------------------------
#define O_STAGE (2*128*LDW + 2*16*LDA)
#define OUT_SMEM (2*O_STAGE*2)

__global__ __launch_bounds__(256, 2) void out_wmma(float* __restrict__ out)
{
    extern __shared__ char smraw[];
    __nv_bfloat16* sbase = (__nv_bfloat16*)smraw;
    const uint32_t sb_u32 = smem_u32(smraw);

    const int tid = threadIdx.x, w = tid >> 5;
    const int b = blockIdx.y, n0 = blockIdx.x * 128;
    const int wm = w & 3, wn = w >> 2;

    const int hl = tid >> 7, gr = tid & 127;
    const __nv_bfloat16* gsrc = (hl ? g_gTl : g_gTh) + (size_t)(b*NC + gr) * NC;
    const int fq0 = (tid & 127) * 2;
    const __nv_bfloat16* fsrc = (hl ? g_Fl : g_Fh);

    auto stage = [&](int st, int kt) {
        const uint32_t sb = sb_u32 + st * O_STAGE * 2;
        const uint32_t gdst = sb + (hl*128*LDW + gr*LDW)*2;
        #pragma unroll
        for (int sg = 0; sg < 2; sg++)
            cp16(gdst + sg*16, gsrc + kt*16 + sg*8);
        const uint32_t fdst = sb + (2*128*LDW + hl*16*LDA)*2;
        #pragma unroll
        for (int q = 0; q < 2; q++) {
            const int idx = fq0 + q, row = idx >> 4, sg = idx & 15;
            cp16(fdst + (row*LDA + sg*8)*2,
                 fsrc + (size_t)(b*NC + kt*16 + row)*HW + n0 + sg*8);
        }
        asm volatile("cp.async.commit_group;");
    };

    stage(0, 0);
    stage(1, 1);

    wmma::fragment<wmma::accumulator, 16, 16, 16, float> acc[2][4];
    #pragma unroll
    for (int mt = 0; mt < 2; mt++)
        #pragma unroll
        for (int nt = 0; nt < 4; nt++)
            wmma::fill_fragment(acc[mt][nt], 0.0f);

    #pragma unroll
    for (int kt = 0; kt < 8; kt++) {
        const int cur = kt & 1;
        if (kt == 7) asm volatile("cp.async.wait_group 0;" ::: "memory");
        else         asm volatile("cp.async.wait_group 1;" ::: "memory");
        __syncthreads();

        __nv_bfloat16* bGh = sbase + cur*O_STAGE;
        __nv_bfloat16* bGl = bGh + 128*LDW;
        __nv_bfloat16* bFh = bGl + 128*LDW;
        __nv_bfloat16* bFl = bFh + 16*LDA;

        wmma::fragment<wmma::matrix_a, 16, 16, 16, __nv_bfloat16, wmma::row_major> ah[2], al[2];
        #pragma unroll
        for (int mt = 0; mt < 2; mt++) {
            const int j0 = wm*32 + mt*16;
            wmma::load_matrix_sync(ah[mt], &bGh[j0*LDW], LDW);
            wmma::load_matrix_sync(al[mt], &bGl[j0*LDW], LDW);
        }
        #pragma unroll
        for (int nt = 0; nt < 4; nt++) {
            wmma::fragment<wmma::matrix_b, 16, 16, 16, __nv_bfloat16, wmma::row_major> bh, bl;
            const int c0 = wn*64 + nt*16;
            wmma::load_matrix_sync(bh, &bFh[c0], LDA);
            wmma::load_matrix_sync(bl, &bFl[c0], LDA);
            #pragma unroll
            for (int mt = 0; mt < 2; mt++) {
                wmma::mma_sync(acc[mt][nt], ah[mt], bh, acc[mt][nt]);
                wmma::mma_sync(acc[mt][nt], ah[mt], bl, acc[mt][nt]);
                wmma::mma_sync(acc[mt][nt], al[mt], bh, acc[mt][nt]);
            }
        }

        __syncthreads();
        if (kt < 6) stage(cur, kt + 2);
    }

    #pragma unroll
    for (int mt = 0; mt < 2; mt++)
        #pragma unroll
        for (int nt = 0; nt < 4; nt++) {
            float* gp = out + ((size_t)b * NC + wm*32 + mt*16) * HW + n0 + wn*64 + nt*16;
            wmma::store_matrix_sync(gp, acc[mt][nt], HW, wmma::mem_row_major);
        }
}

// ---------------------------------------------------------------------------
extern "C" void kernel_launch(void* const* d_in, const int* in_sizes, int n_in,
                              void* d_out, int out_size)
{
    const float* x  = (const float*)d_in[0];
    const float* wA = (const float*)d_in[1];
    const float* bA = (const float*)d_in[2];
    const float* wB = (const float*)d_in[3];
    const float* bB = (const float*)d_in[4];  // unused: softmax shift-invariant
    const float* wV = (const float*)d_in[5];
    const float* bV = (const float*)d_in[6];  // unused: softmax shift-invariant
    (void)bB; (void)bV;
    float* out = (float*)d_out;

    cudaFuncSetAttribute(proj_wmma,    cudaFuncAttributeMaxDynamicSharedMemorySize, PROJ_SMEM);
    cudaFuncSetAttribute(gd_wmma,      cudaFuncAttributeMaxDynamicSharedMemorySize, GD_SMEM);
    cudaFuncSetAttribute(gdgemm_kernel,cudaFuncAttributeMaxDynamicSharedMemorySize, GG_SMEM);
    cudaFuncSetAttribute(out_wmma,     cudaFuncAttributeMaxDynamicSharedMemorySize, OUT_SMEM);

    wconv_kernel <<<2, 256>>>(wB, wV);
    xconv_kernel <<<(NB*NC*HW)/1024, 256>>>(x);
    proj_wmma    <<<dim3(HW/128, NB, 2), 256, PROJ_SMEM>>>();
    gd_wmma      <<<dim3(KSPLIT, NB, 2), 256, GD_SMEM>>>();
    gdgemm_kernel<<<NB, 256, GG_SMEM>>>(wA, bA);
    out_wmma     <<<dim3(HW/128, NB), 256, OUT_SMEM>>>(out);
}

// round 14
// speedup vs baseline: 1.3301x; 1.3301x over previous
#include <cuda_runtime.h>
#include <cuda_bf16.h>
#include <mma.h>
#include <cstdint>

using namespace nvcuda;

#define NB 32
#define NC 128
#define HW 4096
#define NROW (NB*NC)
#define KSPLIT 16

#define LDA 136   // padded ld for 128-wide bf16 rows (272B -> conflict-free)
#define LDW 24    // padded ld for 16-wide bf16 k-chunks
#define LDK 40    // padded ld for 32-wide bf16 k-chunks (80B rows)

// Scratch (device globals: allocation-free kernel_launch)
__device__ __align__(16) __nv_bfloat16 g_xh[NB*NC*HW], g_xl[NB*NC*HW];   // x pair
__device__ __align__(16) __nv_bfloat16 g_Eh[NB*NC*HW], g_El[NB*NC*HW];   // exp(B)
__device__ __align__(16) __nv_bfloat16 g_Fh[NB*NC*HW], g_Fl[NB*NC*HW];   // exp(V)
__device__ float g_gdp[KSPLIT*NB*NC*NC];          // partials of M = E @ x^T
__device__ __align__(16) __nv_bfloat16 g_gTh[NB*NC*NC];   // gd'^T [b][j][i]
__device__ __align__(16) __nv_bfloat16 g_gTl[NB*NC*NC];
__device__ float g_zBp[32*NROW], g_zVp[32*NROW];  // per-nblock partial exp sums
__device__ __align__(16) __nv_bfloat16 g_wh[2*NC*NC], g_wl[2*NC*NC];  // wB, wV pairs

__device__ __forceinline__ void split_bf16(float f, __nv_bfloat16& h, __nv_bfloat16& l) {
    h = __float2bfloat16(f);
    l = __float2bfloat16(f - __bfloat162float(h));
}
__device__ __forceinline__ void cp16(uint32_t saddr, const void* g) {
    asm volatile("cp.async.ca.shared.global [%0], [%1], 16;" :: "r"(saddr), "l"(g));
}
__device__ __forceinline__ uint32_t smem_u32(const void* p) {
    uint32_t a;
    asm("{ .reg .u64 t; cvta.to.shared.u64 t, %1; cvt.u32.u64 %0, t; }" : "=r"(a) : "l"(p));
    return a;
}

// ---------------------------------------------------------------------------
// Kernel W: wB, wV -> bf16 hi/lo (wA stays fp32; used exactly in gdgemm)
// ---------------------------------------------------------------------------
__global__ __launch_bounds__(256) void wconv_kernel(
    const float* __restrict__ wB, const float* __restrict__ wV)
{
    const float* ws[2] = {wB, wV};
    const int m = blockIdx.x;
    const float* w = ws[m];
    for (int idx = threadIdx.x; idx < NC*NC; idx += 256) {
        __nv_bfloat16 h, l;
        split_bf16(w[idx], h, l);
        g_wh[m*NC*NC + idx] = h;
        g_wl[m*NC*NC + idx] = l;
    }
}

// ---------------------------------------------------------------------------
// Kernel X: x fp32 -> bf16 hi/lo pair (one-time)
// ---------------------------------------------------------------------------
__global__ __launch_bounds__(256) void xconv_kernel(const float* __restrict__ x)
{
    const size_t i0 = ((size_t)blockIdx.x * 256 + threadIdx.x) * 4;
    float4 v = *(const float4*)(x + i0);
    __nv_bfloat16 h0, l0, h1, l1, h2, l2, h3, l3;
    split_bf16(v.x, h0, l0);
    split_bf16(v.y, h1, l1);
    split_bf16(v.z, h2, l2);
    split_bf16(v.w, h3, l3);
    *(__nv_bfloat162*)&g_xh[i0]     = __halves2bfloat162(h0, h1);
    *(__nv_bfloat162*)&g_xh[i0 + 2] = __halves2bfloat162(h2, h3);
    *(__nv_bfloat162*)&g_xl[i0]     = __halves2bfloat162(l0, l1);
    *(__nv_bfloat162*)&g_xl[i0 + 2] = __halves2bfloat162(l2, l3);
}

// ---------------------------------------------------------------------------
// Kernel P (R10 config restored): E/F projections (m = blockIdx.z).
// 3-term split. W(pair) + X(pair) streamed via cp.async 2-stage pipeline.
// block 128o x 128n, warp 32x64, 256 thr, 2 blk/SM (NO reg cap -> no spills).
// ---------------------------------------------------------------------------
#define P_STAGE (2*128*LDK + 2*32*LDA)
#define PROJ_SMEM (2*P_STAGE*2 + 8*16*20*4 + 128*4*4)

__global__ __launch_bounds__(256, 2) void proj_wmma()
{
    extern __shared__ char smraw[];
    __nv_bfloat16* sbase = (__nv_bfloat16*)smraw;
    const uint32_t sb_u32 = smem_u32(smraw);
    float* stage = (float*)(sbase + 2*P_STAGE);       // 8 warps x 16x20
    float* zsm   = stage + 8*16*20;                   // [128][4]

    const int tid = threadIdx.x, w = tid >> 5, lane = tid & 31;
    const int b = blockIdx.y, n0 = blockIdx.x * 128;
    const int m = blockIdx.z;
    const int wm = w & 3, wn = w >> 2;

    // staging maps
    const int whl = tid >> 7, wr = tid & 127;
    const int xq0 = (tid & 127) * 4;
    const __nv_bfloat16* xsrc = (whl ? g_xl : g_xh);
    const __nv_bfloat16* wsrc0 = (whl ? g_wl : g_wh) + m*NC*NC + wr*NC;

    auto stage_cp = [&](int st, int kt) {
        const uint32_t sb = sb_u32 + st * P_STAGE * 2;
        const __nv_bfloat16* wsrc = wsrc0 + kt*32;
        const uint32_t wdst = sb + (whl*128*LDK + wr*LDK)*2;
        #pragma unroll
        for (int sg = 0; sg < 4; sg++)
            cp16(wdst + sg*16, wsrc + sg*8);
        const uint32_t xdst = sb + (2*128*LDK + whl*32*LDA)*2;
        #pragma unroll
        for (int q = 0; q < 4; q++) {
            const int idx = xq0 + q, row = idx >> 4, sg = idx & 15;
            cp16(xdst + (row*LDA + sg*8)*2,
                 xsrc + ((size_t)(b*NC + kt*32 + row))*HW + n0 + sg*8);
        }
        asm volatile("cp.async.commit_group;");
    };

    stage_cp(0, 0);
    stage_cp(1, 1);

    wmma::fragment<wmma::accumulator, 16, 16, 16, float> acc[2][4];
    #pragma unroll
    for (int mt = 0; mt < 2; mt++)
        #pragma unroll
        for (int nt = 0; nt < 4; nt++)
            wmma::fill_fragment(acc[mt][nt], 0.0f);

    #pragma unroll
    for (int kt = 0; kt < 4; kt++) {
        const int cur = kt & 1;
        if (kt == 3) asm volatile("cp.async.wait_group 0;" ::: "memory");
        else         asm volatile("cp.async.wait_group 1;" ::: "memory");
        __syncthreads();

        __nv_bfloat16* sWh = sbase + cur*P_STAGE;
        __nv_bfloat16* sWl = sWh + 128*LDK;
        __nv_bfloat16* sXh = sWl + 128*LDK;
        __nv_bfloat16* sXl = sXh + 32*LDA;

        #pragma unroll
        for (int kk = 0; kk < 2; kk++) {
            wmma::fragment<wmma::matrix_a, 16, 16, 16, __nv_bfloat16, wmma::row_major> ah[2], al[2];
            #pragma unroll
            for (int mt = 0; mt < 2; mt++) {
                const int o0 = wm*32 + mt*16;
                wmma::load_matrix_sync(ah[mt], &sWh[o0*LDK + kk*16], LDK);
                wmma::load_matrix_sync(al[mt], &sWl[o0*LDK + kk*16], LDK);
            }
            #pragma unroll
            for (int nt = 0; nt < 4; nt++) {
                wmma::fragment<wmma::matrix_b, 16, 16, 16, __nv_bfloat16, wmma::row_major> bh, bl;
                const int c0 = wn*64 + nt*16;
                wmma::load_matrix_sync(bh, &sXh[kk*16*LDA + c0], LDA);
                wmma::load_matrix_sync(bl, &sXl[kk*16*LDA + c0], LDA);
                #pragma unroll
                for (int mt = 0; mt < 2; mt++) {
                    wmma::mma_sync(acc[mt][nt], ah[mt], bh, acc[mt][nt]);
                    wmma::mma_sync(acc[mt][nt], ah[mt], bl, acc[mt][nt]);
                    wmma::mma_sync(acc[mt][nt], al[mt], bh, acc[mt][nt]);
                }
            }
        }

        __syncthreads();
        if (kt < 2) stage_cp(cur, kt + 2);
    }

    // Epilogue: exp, split, store pair + row partial sums
    float* st = stage + w * 16 * 20;
    float rs0 = 0.f, rs1 = 0.f;
    __nv_bfloat16* dh = (m == 0) ? g_Eh : g_Fh;
    __nv_bfloat16* dl = (m == 0) ? g_El : g_Fl;
    #pragma unroll
    for (int mt = 0; mt < 2; mt++)
        #pragma unroll
        for (int nt = 0; nt < 4; nt++) {
            wmma::store_matrix_sync(st, acc[mt][nt], 20, wmma::mem_row_major);
            __syncwarp();
            const int r = lane & 15, c8 = (lane >> 4) * 8;
            const int o = wm*32 + mt*16 + r;
            const int nn = n0 + wn*64 + nt*16 + c8;
            const float* sp = st + r*20 + c8;
            const size_t gb = ((size_t)b * NC + o) * HW + nn;
            float v[8];
            float lsum = 0.f;
            #pragma unroll
            for (int k = 0; k < 8; k++) { v[k] = __expf(sp[k]); lsum += v[k]; }
            if (mt == 0) rs0 += lsum; else rs1 += lsum;
            #pragma unroll
            for (int k = 0; k < 8; k += 2) {
                __nv_bfloat16 h0, l0, h1, l1;
                split_bf16(v[k],   h0, l0);
                split_bf16(v[k+1], h1, l1);
                *(__nv_bfloat162*)&dh[gb + k] = __halves2bfloat162(h0, h1);
                *(__nv_bfloat162*)&dl[gb + k] = __halves2bfloat162(l0, l1);
            }
            __syncwarp();
        }

    {
        const int idx = wn*2 + (lane >> 4), r = lane & 15;
        zsm[(wm*32 + r)*4 + idx]      = rs0;
        zsm[(wm*32 + 16 + r)*4 + idx] = rs1;
        __syncthreads();
        if (tid < 128) {
            float z = zsm[tid*4] + zsm[tid*4+1] + zsm[tid*4+2] + zsm[tid*4+3];
            float* zp = (m == 0) ? g_zBp : g_zVp;
            zp[blockIdx.x*NROW + b*NC + tid] = z;
        }
    }
}

// ---------------------------------------------------------------------------
// Kernel G: M partials: gdp[s][b][i][c] = sum_{n in 256-chunk} E[i,n]*x[c,n]
// block 128i x 64c (ch via blockIdx.z), warp 32x32, 256 thr, 3 blk/SM.
// cp.async 2-stage pipeline, k-chunk 32.  (3-term split)
// ---------------------------------------------------------------------------
#define GD_STAGE (2*128*LDK + 2*64*LDK)
#define GD_SMEM  (2*GD_STAGE*2)

__global__ __launch_bounds__(256, 3) void gd_wmma()
{
    extern __shared__ char smraw[];
    __nv_bfloat16* sbase = (__nv_bfloat16*)smraw;
    const uint32_t sb_u32 = smem_u32(smraw);

    const int tid = threadIdx.x, w = tid >> 5;
    const int s = blockIdx.x, b = blockIdx.y, jh = blockIdx.z;
    const int kbase = s * 256;
    const int wi = w & 3, wj = w >> 2;

    const int er = tid >> 1;
    const int es = (tid & 1) * 2;
    const int ar = tid >> 2, as_ = tid & 3;

    const __nv_bfloat16* Ehp = g_Eh + (size_t)(b*NC + er) * HW;
    const __nv_bfloat16* Elp = g_El + (size_t)(b*NC + er) * HW;
    const __nv_bfloat16* Ahp = g_xh + (size_t)(b*NC + jh*64 + ar) * HW;
    const __nv_bfloat16* Alp = g_xl + (size_t)(b*NC + jh*64 + ar) * HW;

    auto stage = [&](int st, int kt) {
        const int kk0 = kbase + kt * 32;
        const uint32_t sb = sb_u32 + st * GD_STAGE * 2;
        #pragma unroll
        for (int q = 0; q < 2; q++) {
            const int sg = es + q;
            cp16(sb + (er*LDK + sg*8)*2,           Ehp + kk0 + sg*8);
            cp16(sb + (128*LDK + er*LDK + sg*8)*2, Elp + kk0 + sg*8);
        }
        cp16(sb + (2*128*LDK + ar*LDK + as_*8)*2,          Ahp + kk0 + as_*8);
        cp16(sb + (2*128*LDK + 64*LDK + ar*LDK + as_*8)*2, Alp + kk0 + as_*8);
        asm volatile("cp.async.commit_group;");
    };

    stage(0, 0);
    stage(1, 1);

    wmma::fragment<wmma::accumulator, 16, 16, 16, float> acc[2][2];
    #pragma unroll
    for (int mt = 0; mt < 2; mt++)
        #pragma unroll
        for (int nt = 0; nt < 2; nt++)
            wmma::fill_fragment(acc[mt][nt], 0.0f);

    #pragma unroll
    for (int kt = 0; kt < 8; kt++) {
        const int cur = kt & 1;
        if (kt == 7) asm volatile("cp.async.wait_group 0;" ::: "memory");
        else         asm volatile("cp.async.wait_group 1;" ::: "memory");
        __syncthreads();

        __nv_bfloat16* sEh = sbase + cur*GD_STAGE;
        __nv_bfloat16* sEl = sEh + 128*LDK;
        __nv_bfloat16* sAh = sEl + 128*LDK;
        __nv_bfloat16* sAl = sAh + 64*LDK;

        #pragma unroll
        for (int kk = 0; kk < 2; kk++) {
            wmma::fragment<wmma::matrix_a, 16, 16, 16, __nv_bfloat16, wmma::row_major> ah[2], al[2];
            #pragma unroll
            for (int mt = 0; mt < 2; mt++) {
                const int i0 = wi*32 + mt*16;
                wmma::load_matrix_sync(ah[mt], &sEh[i0*LDK + kk*16], LDK);
                wmma::load_matrix_sync(al[mt], &sEl[i0*LDK + kk*16], LDK);
            }
            #pragma unroll
            for (int nt = 0; nt < 2; nt++) {
                wmma::fragment<wmma::matrix_b, 16, 16, 16, __nv_bfloat16, wmma::col_major> bh, bl;
                const int j0 = wj*32 + nt*16;
                wmma::load_matrix_sync(bh, &sAh[j0*LDK + kk*16], LDK);
                wmma::load_matrix_sync(bl, &sAl[j0*LDK + kk*16], LDK);
                #pragma unroll
                for (int mt = 0; mt < 2; mt++) {
                    wmma::mma_sync(acc[mt][nt], ah[mt], bh, acc[mt][nt]);
                    wmma::mma_sync(acc[mt][nt], ah[mt], bl, acc[mt][nt]);
                    wmma::mma_sync(acc[mt][nt], al[mt], bh, acc[mt][nt]);
                }
            }
        }

        __syncthreads();
        if (kt < 6) stage(cur, kt + 2);
    }

    float* gp = g_gdp + ((size_t)s * NB + b) * NC * NC;
    #pragma unroll
    for (int mt = 0; mt < 2; mt++)
        #pragma unroll
        for (int nt = 0; nt < 2; nt++)
            wmma::store_matrix_sync(gp + (wi*32 + mt*16) * NC + jh*64 + wj*32 + nt*16,
                                    acc[mt][nt], NC, wmma::mem_row_major);
}

// ---------------------------------------------------------------------------
// Kernel S2 (FUSED, kept from R13): per-b block computes
//   scl/bscl rows (from z-partials), M = sum_s gdp[s], then
//   gd'^T[b][j][i] = (sum_c M[i][c]*wA[j][c])*scl[i] + bA[j]*bscl[i]
// Exact fp32. grid 32 blocks, 256 threads (16x16), 8jx8i microtile.
// ---------------------------------------------------------------------------
#define LDR 132
#define GG_SMEM (2*128*LDR*4 + 2*128*4)

__global__ __launch_bounds__(256, 1) void gdgemm_kernel(
    const float* __restrict__ wA, const float* __restrict__ bA)
{
    extern __shared__ char smraw[];
    float* sM = (float*)smraw;          // [c][i]
    float* sW = sM + 128*LDR;           // [c][j]
    float* sscl  = sW + 128*LDR;        // [128]
    float* sbscl = sscl + 128;          // [128]

    const int b = blockIdx.x, tid = threadIdx.x;
    const int tx = tid & 15, ty = tid >> 4;

    if (tid < 128) {
        const int row = b * NC + tid;
        float zb = 0.f, zv = 0.f;
        #pragma unroll
        for (int nb = 0; nb < 32; nb++) {
            zb += g_zBp[nb*NROW + row];
            zv += g_zVp[nb*NROW + row];
        }
        sscl[tid]  = 1.0f / (zb * (float)HW * zv);
        sbscl[tid] = 1.0f / ((float)HW * zv);
    }

    for (int idx = tid; idx < NC*NC; idx += 256) {
        const int r = idx >> 7, c = idx & 127;
        float sum = 0.f;
        #pragma unroll
        for (int s = 0; s < KSPLIT; s++)
            sum += g_gdp[(size_t)s * (NB*NC*NC) + b*NC*NC + idx];
        sM[c*LDR + r] = sum;
        sW[c*LDR + r] = wA[idx];
    }
    __syncthreads();

    float acc[8][8];
    #pragma unroll
    for (int a = 0; a < 8; a++)
        #pragma unroll
        for (int d = 0; d < 8; d++) acc[a][d] = 0.f;

    for (int c = 0; c < 128; c++) {
        float4 j0 = *(const float4*)&sW[c*LDR + ty*8];
        float4 j1 = *(const float4*)&sW[c*LDR + ty*8 + 4];
        float4 i0 = *(const float4*)&sM[c*LDR + tx*8];
        float4 i1 = *(const float4*)&sM[c*LDR + tx*8 + 4];
        const float jv[8] = {j0.x, j0.y, j0.z, j0.w, j1.x, j1.y, j1.z, j1.w};
        const float iv[8] = {i0.x, i0.y, i0.z, i0.w, i1.x, i1.y, i1.z, i1.w};
        #pragma unroll
        for (int a = 0; a < 8; a++)
            #pragma unroll
            for (int d = 0; d < 8; d++)
                acc[a][d] += jv[a] * iv[d];
    }

    #pragma unroll
    for (int a = 0; a < 8; a++) {
        const int j = ty*8 + a;
        const float bAj = bA[j];
        #pragma unroll
        for (int d = 0; d < 8; d += 2) {
            const int i = tx*8 + d;
            const float v0 = acc[a][d]   * sscl[i]   + bAj * sbscl[i];
            const float v1 = acc[a][d+1] * sscl[i+1] + bAj * sbscl[i+1];
            __nv_bfloat16 h0, l0, h1, l1;
            split_bf16(v0, h0, l0);
            split_bf16(v1, h1, l1);
            const size_t t = (size_t)b*NC*NC + (size_t)j*NC + i;
            *(__nv_bfloat162*)&g_gTh[t] = __halves2bfloat162(h0, h1);
            *(__nv_bfloat162*)&g_gTl[t] = __halves2bfloat162(l0, l1);
        }
    }
}

// ---------------------------------------------------------------------------
// Kernel O: out[b,j,n] = sum_i F[i,n]*gd'[i,j]  (3-term bf16 GEMM, K=128)
// cp.async 2-stage, k-chunk 16. grid (HW/128, NB), 256 thr, block 128j x 128n.
// ---------------------------------------------------------------------------
#define O_STAGE (2*128*LDW + 2*16*LDA)
#define OUT_SMEM (2*O_STAGE*2)

__global__ __launch_bounds__(256, 2) void out_wmma(float* __restrict__ out)
{
    extern __shared__ char smraw[];
    __nv_bfloat16* sbase = (__nv_bfloat16*)smraw;
    const uint32_t sb_u32 = smem_u32(smraw);

    const int tid = threadIdx.x, w = tid >> 5;
    const int b = blockIdx.y, n0 = blockIdx.x * 128;
    const int wm = w & 3, wn = w >> 2;

    const int hl = tid >> 7, gr = tid & 127;
    const __nv_bfloat16* gsrc = (hl ? g_gTl : g_gTh) + (size_t)(b*NC + gr) * NC;
    const int fq0 = (tid & 127) * 2;
    const __nv_bfloat16* fsrc = (hl ? g_Fl : g_Fh);

    auto stage = [&](int st, int kt) {
        const uint32_t sb = sb_u32 + st * O_STAGE * 2;
        const uint32_t gdst = sb + (hl*128*LDW + gr*LDW)*2;
        #pragma unroll
        for (int sg = 0; sg < 2; sg++)
            cp16(gdst + sg*16, gsrc + kt*16 + sg*8);
        const uint32_t fdst = sb + (2*128*LDW + hl*16*LDA)*2;
        #pragma unroll
        for (int q = 0; q < 2; q++) {
            const int idx = fq0 + q, row = idx >> 4, sg = idx & 15;
            cp16(fdst + (row*LDA + sg*8)*2,
                 fsrc + (size_t)(b*NC + kt*16 + row)*HW + n0 + sg*8);
        }
        asm volatile("cp.async.commit_group;");
    };

    stage(0, 0);
    stage(1, 1);

    wmma::fragment<wmma::accumulator, 16, 16, 16, float> acc[2][4];
    #pragma unroll
    for (int mt = 0; mt < 2; mt++)
        #pragma unroll
        for (int nt = 0; nt < 4; nt++)
            wmma::fill_fragment(acc[mt][nt], 0.0f);

    #pragma unroll
    for (int kt = 0; kt < 8; kt++) {
        const int cur = kt & 1;
        if (kt == 7) asm volatile("cp.async.wait_group 0;" ::: "memory");
        else         asm volatile("cp.async.wait_group 1;" ::: "memory");
        __syncthreads();

        __nv_bfloat16* bGh = sbase + cur*O_STAGE;
        __nv_bfloat16* bGl = bGh + 128*LDW;
        __nv_bfloat16* bFh = bGl + 128*LDW;
        __nv_bfloat16* bFl = bFh + 16*LDA;

        wmma::fragment<wmma::matrix_a, 16, 16, 16, __nv_bfloat16, wmma::row_major> ah[2], al[2];
        #pragma unroll
        for (int mt = 0; mt < 2; mt++) {
            const int j0 = wm*32 + mt*16;
            wmma::load_matrix_sync(ah[mt], &bGh[j0*LDW], LDW);
            wmma::load_matrix_sync(al[mt], &bGl[j0*LDW], LDW);
        }
        #pragma unroll
        for (int nt = 0; nt < 4; nt++) {
            wmma::fragment<wmma::matrix_b, 16, 16, 16, __nv_bfloat16, wmma::row_major> bh, bl;
            const int c0 = wn*64 + nt*16;
            wmma::load_matrix_sync(bh, &bFh[c0], LDA);
            wmma::load_matrix_sync(bl, &bFl[c0], LDA);
            #pragma unroll
            for (int mt = 0; mt < 2; mt++) {
                wmma::mma_sync(acc[mt][nt], ah[mt], bh, acc[mt][nt]);
                wmma::mma_sync(acc[mt][nt], ah[mt], bl, acc[mt][nt]);
                wmma::mma_sync(acc[mt][nt], al[mt], bh, acc[mt][nt]);
            }
        }

        __syncthreads();
        if (kt < 6) stage(cur, kt + 2);
    }

    #pragma unroll
    for (int mt = 0; mt < 2; mt++)
        #pragma unroll
        for (int nt = 0; nt < 4; nt++) {
            float* gp = out + ((size_t)b * NC + wm*32 + mt*16) * HW + n0 + wn*64 + nt*16;
            wmma::store_matrix_sync(gp, acc[mt][nt], HW, wmma::mem_row_major);
        }
}

// ---------------------------------------------------------------------------
extern "C" void kernel_launch(void* const* d_in, const int* in_sizes, int n_in,
                              void* d_out, int out_size)
{
    const float* x  = (const float*)d_in[0];
    const float* wA = (const float*)d_in[1];
    const float* bA = (const float*)d_in[2];
    const float* wB = (const float*)d_in[3];
    const float* bB = (const float*)d_in[4];  // unused: softmax shift-invariant
    const float* wV = (const float*)d_in[5];
    const float* bV = (const float*)d_in[6];  // unused: softmax shift-invariant
    (void)bB; (void)bV;
    float* out = (float*)d_out;

    cudaFuncSetAttribute(proj_wmma,    cudaFuncAttributeMaxDynamicSharedMemorySize, PROJ_SMEM);
    cudaFuncSetAttribute(gd_wmma,      cudaFuncAttributeMaxDynamicSharedMemorySize, GD_SMEM);
    cudaFuncSetAttribute(gdgemm_kernel,cudaFuncAttributeMaxDynamicSharedMemorySize, GG_SMEM);
    cudaFuncSetAttribute(out_wmma,     cudaFuncAttributeMaxDynamicSharedMemorySize, OUT_SMEM);

    wconv_kernel <<<2, 256>>>(wB, wV);
    xconv_kernel <<<(NB*NC*HW)/1024, 256>>>(x);
    proj_wmma    <<<dim3(HW/128, NB, 2), 256, PROJ_SMEM>>>();
    gd_wmma      <<<dim3(KSPLIT, NB, 2), 256, GD_SMEM>>>();
    gdgemm_kernel<<<NB, 256, GG_SMEM>>>(wA, bA);
    out_wmma     <<<dim3(HW/128, NB), 256, OUT_SMEM>>>(out);
}

// round 15
// speedup vs baseline: 1.3619x; 1.0239x over previous
#include <cuda_runtime.h>
#include <cuda_bf16.h>
#include <mma.h>
#include <cstdint>

using namespace nvcuda;

#define NB 32
#define NC 128
#define HW 4096
#define NROW (NB*NC)
#define KSPLIT 16

#define LDA 136   // padded ld for 128-wide bf16 rows (272B -> conflict-free)
#define LDW 24    // padded ld for 16-wide bf16 k-chunks
#define LDK 40    // padded ld for 32-wide bf16 k-chunks (80B rows)

// Scratch (device globals: allocation-free kernel_launch)
__device__ __align__(16) __nv_bfloat16 g_xh[NB*NC*HW], g_xl[NB*NC*HW];   // x pair
__device__ __align__(16) __nv_bfloat16 g_Eh[NB*NC*HW], g_El[NB*NC*HW];   // exp(B)
__device__ __align__(16) __nv_bfloat16 g_Fh[NB*NC*HW], g_Fl[NB*NC*HW];   // exp(V)
__device__ float g_gdp[KSPLIT*NB*NC*NC];          // partials of M = E @ x^T
__device__ float g_gds[NB*NC*NC];                 // M summed over splits
__device__ __align__(16) __nv_bfloat16 g_gTh[NB*NC*NC];   // gd'^T [b][j][i]
__device__ __align__(16) __nv_bfloat16 g_gTl[NB*NC*NC];
__device__ float g_zBp[32*NROW], g_zVp[32*NROW];
__device__ float g_scl[NROW], g_bscl[NROW];       // 1/(zB*HW*zV), 1/(HW*zV)
__device__ __align__(16) __nv_bfloat16 g_wh[2*NC*NC], g_wl[2*NC*NC];  // wB, wV pairs

__device__ __forceinline__ void split_bf16(float f, __nv_bfloat16& h, __nv_bfloat16& l) {
    h = __float2bfloat16(f);
    l = __float2bfloat16(f - __bfloat162float(h));
}
__device__ __forceinline__ void cp16(uint32_t saddr, const void* g) {
    asm volatile("cp.async.ca.shared.global [%0], [%1], 16;" :: "r"(saddr), "l"(g));
}
__device__ __forceinline__ uint32_t smem_u32(const void* p) {
    uint32_t a;
    asm("{ .reg .u64 t; cvta.to.shared.u64 t, %1; cvt.u32.u64 %0, t; }" : "=r"(a) : "l"(p));
    return a;
}

// ---------------------------------------------------------------------------
// Kernel W: wB, wV -> bf16 hi/lo (wA stays fp32; used exactly in gdgemm)
// ---------------------------------------------------------------------------
__global__ __launch_bounds__(256) void wconv_kernel(
    const float* __restrict__ wB, const float* __restrict__ wV)
{
    const float* ws[2] = {wB, wV};
    const int m = blockIdx.x;
    const float* w = ws[m];
    for (int idx = threadIdx.x; idx < NC*NC; idx += 256) {
        __nv_bfloat16 h, l;
        split_bf16(w[idx], h, l);
        g_wh[m*NC*NC + idx] = h;
        g_wl[m*NC*NC + idx] = l;
    }
}

// ---------------------------------------------------------------------------
// Kernel X: x fp32 -> bf16 hi/lo pair (one-time)
// ---------------------------------------------------------------------------
__global__ __launch_bounds__(256) void xconv_kernel(const float* __restrict__ x)
{
    const size_t i0 = ((size_t)blockIdx.x * 256 + threadIdx.x) * 4;
    float4 v = *(const float4*)(x + i0);
    __nv_bfloat16 h0, l0, h1, l1, h2, l2, h3, l3;
    split_bf16(v.x, h0, l0);
    split_bf16(v.y, h1, l1);
    split_bf16(v.z, h2, l2);
    split_bf16(v.w, h3, l3);
    *(__nv_bfloat162*)&g_xh[i0]     = __halves2bfloat162(h0, h1);
    *(__nv_bfloat162*)&g_xh[i0 + 2] = __halves2bfloat162(h2, h3);
    *(__nv_bfloat162*)&g_xl[i0]     = __halves2bfloat162(l0, l1);
    *(__nv_bfloat162*)&g_xl[i0 + 2] = __halves2bfloat162(l2, l3);
}

// ---------------------------------------------------------------------------
// Kernel P: E/F projections (m = blockIdx.z: 0 -> exp(wB x), 1 -> exp(wV x)).
// 3-term split. W(pair) + X(pair) streamed via cp.async 2-stage pipeline.
// block 128o x 128n, warp 32x64, 256 thr, 2 blk/SM.  (R10 config)
// ---------------------------------------------------------------------------
#define P_STAGE (2*128*LDK + 2*32*LDA)
#define PROJ_SMEM (2*P_STAGE*2 + 8*16*20*4 + 128*4*4)

__global__ __launch_bounds__(256, 2) void proj_wmma()
{
    extern __shared__ char smraw[];
    __nv_bfloat16* sbase = (__nv_bfloat16*)smraw;
    const uint32_t sb_u32 = smem_u32(smraw);
    float* stage = (float*)(sbase + 2*P_STAGE);       // 8 warps x 16x20
    float* zsm   = stage + 8*16*20;                   // [128][4]

    const int tid = threadIdx.x, w = tid >> 5, lane = tid & 31;
    const int b = blockIdx.y, n0 = blockIdx.x * 128;
    const int m = blockIdx.z;
    const int wm = w & 3, wn = w >> 2;

    const int whl = tid >> 7, wr = tid & 127;
    const int xq0 = (tid & 127) * 4;
    const __nv_bfloat16* xsrc = (whl ? g_xl : g_xh);
    const __nv_bfloat16* wsrc0 = (whl ? g_wl : g_wh) + m*NC*NC + wr*NC;

    auto stage_cp = [&](int st, int kt) {
        const uint32_t sb = sb_u32 + st * P_STAGE * 2;
        const __nv_bfloat16* wsrc = wsrc0 + kt*32;
        const uint32_t wdst = sb + (whl*128*LDK + wr*LDK)*2;
        #pragma unroll
        for (int sg = 0; sg < 4; sg++)
            cp16(wdst + sg*16, wsrc + sg*8);
        const uint32_t xdst = sb + (2*128*LDK + whl*32*LDA)*2;
        #pragma unroll
        for (int q = 0; q < 4; q++) {
            const int idx = xq0 + q, row = idx >> 4, sg = idx & 15;
            cp16(xdst + (row*LDA + sg*8)*2,
                 xsrc + ((size_t)(b*NC + kt*32 + row))*HW + n0 + sg*8);
        }
        asm volatile("cp.async.commit_group;");
    };

    stage_cp(0, 0);
    stage_cp(1, 1);

    wmma::fragment<wmma::accumulator, 16, 16, 16, float> acc[2][4];
    #pragma unroll
    for (int mt = 0; mt < 2; mt++)
        #pragma unroll
        for (int nt = 0; nt < 4; nt++)
            wmma::fill_fragment(acc[mt][nt], 0.0f);

    #pragma unroll
    for (int kt = 0; kt < 4; kt++) {
        const int cur = kt & 1;
        if (kt == 3) asm volatile("cp.async.wait_group 0;" ::: "memory");
        else         asm volatile("cp.async.wait_group 1;" ::: "memory");
        __syncthreads();

        __nv_bfloat16* sWh = sbase + cur*P_STAGE;
        __nv_bfloat16* sWl = sWh + 128*LDK;
        __nv_bfloat16* sXh = sWl + 128*LDK;
        __nv_bfloat16* sXl = sXh + 32*LDA;

        #pragma unroll
        for (int kk = 0; kk < 2; kk++) {
            wmma::fragment<wmma::matrix_a, 16, 16, 16, __nv_bfloat16, wmma::row_major> ah[2], al[2];
            #pragma unroll
            for (int mt = 0; mt < 2; mt++) {
                const int o0 = wm*32 + mt*16;
                wmma::load_matrix_sync(ah[mt], &sWh[o0*LDK + kk*16], LDK);
                wmma::load_matrix_sync(al[mt], &sWl[o0*LDK + kk*16], LDK);
            }
            #pragma unroll
            for (int nt = 0; nt < 4; nt++) {
                wmma::fragment<wmma::matrix_b, 16, 16, 16, __nv_bfloat16, wmma::row_major> bh, bl;
                const int c0 = wn*64 + nt*16;
                wmma::load_matrix_sync(bh, &sXh[kk*16*LDA + c0], LDA);
                wmma::load_matrix_sync(bl, &sXl[kk*16*LDA + c0], LDA);
                #pragma unroll
                for (int mt = 0; mt < 2; mt++) {
                    wmma::mma_sync(acc[mt][nt], ah[mt], bh, acc[mt][nt]);
                    wmma::mma_sync(acc[mt][nt], ah[mt], bl, acc[mt][nt]);
                    wmma::mma_sync(acc[mt][nt], al[mt], bh, acc[mt][nt]);
                }
            }
        }

        __syncthreads();
        if (kt < 2) stage_cp(cur, kt + 2);
    }

    // Epilogue: exp, split, store pair + row partial sums
    float* st = stage + w * 16 * 20;
    float rs0 = 0.f, rs1 = 0.f;
    __nv_bfloat16* dh = (m == 0) ? g_Eh : g_Fh;
    __nv_bfloat16* dl = (m == 0) ? g_El : g_Fl;
    #pragma unroll
    for (int mt = 0; mt < 2; mt++)
        #pragma unroll
        for (int nt = 0; nt < 4; nt++) {
            wmma::store_matrix_sync(st, acc[mt][nt], 20, wmma::mem_row_major);
            __syncwarp();
            const int r = lane & 15, c8 = (lane >> 4) * 8;
            const int o = wm*32 + mt*16 + r;
            const int nn = n0 + wn*64 + nt*16 + c8;
            const float* sp = st + r*20 + c8;
            const size_t gb = ((size_t)b * NC + o) * HW + nn;
            float v[8];
            float lsum = 0.f;
            #pragma unroll
            for (int k = 0; k < 8; k++) { v[k] = __expf(sp[k]); lsum += v[k]; }
            if (mt == 0) rs0 += lsum; else rs1 += lsum;
            #pragma unroll
            for (int k = 0; k < 8; k += 2) {
                __nv_bfloat16 h0, l0, h1, l1;
                split_bf16(v[k],   h0, l0);
                split_bf16(v[k+1], h1, l1);
                *(__nv_bfloat162*)&dh[gb + k] = __halves2bfloat162(h0, h1);
                *(__nv_bfloat162*)&dl[gb + k] = __halves2bfloat162(l0, l1);
            }
            __syncwarp();
        }

    {
        const int idx = wn*2 + (lane >> 4), r = lane & 15;
        zsm[(wm*32 + r)*4 + idx]      = rs0;
        zsm[(wm*32 + 16 + r)*4 + idx] = rs1;
        __syncthreads();
        if (tid < 128) {
            float z = zsm[tid*4] + zsm[tid*4+1] + zsm[tid*4+2] + zsm[tid*4+3];
            float* zp = (m == 0) ? g_zBp : g_zVp;
            zp[blockIdx.x*NROW + b*NC + tid] = z;
        }
    }
}

// ---------------------------------------------------------------------------
// Kernel Z: finalize per-row scales (deterministic sum of 32 partials)
// ---------------------------------------------------------------------------
__global__ __launch_bounds__(256) void zfin_kernel()
{
    const int row = blockIdx.x * 256 + threadIdx.x;   // < NROW
    float zb = 0.f, zv = 0.f;
    #pragma unroll
    for (int nb = 0; nb < 32; nb++) {
        zb += g_zBp[nb*NROW + row];
        zv += g_zVp[nb*NROW + row];
    }
    g_scl[row]  = 1.0f / (zb * (float)HW * zv);
    g_bscl[row] = 1.0f / ((float)HW * zv);
}

// ---------------------------------------------------------------------------
// Kernel G: M partials: gdp[s][b][i][c] = sum_{n in 256-chunk} E[i,n]*x[c,n]
// block 128i x 64c (ch via blockIdx.z), warp 32x32, 256 thr, 3 blk/SM.
// cp.async 2-stage pipeline, k-chunk 32.  (3-term split)
// ---------------------------------------------------------------------------
#define GD_STAGE (2*128*LDK + 2*64*LDK)
#define GD_SMEM  (2*GD_STAGE*2)

__global__ __launch_bounds__(256, 3) void gd_wmma()
{
    extern __shared__ char smraw[];
    __nv_bfloat16* sbase = (__nv_bfloat16*)smraw;
    const uint32_t sb_u32 = smem_u32(smraw);

    const int tid = threadIdx.x, w = tid >> 5;
    const int s = blockIdx.x, b = blockIdx.y, jh = blockIdx.z;
    const int kbase = s * 256;
    const int wi = w & 3, wj = w >> 2;

    const int er = tid >> 1;
    const int es = (tid & 1) * 2;
    const int ar = tid >> 2, as_ = tid & 3;

    const __nv_bfloat16* Ehp = g_Eh + (size_t)(b*NC + er) * HW;
    const __nv_bfloat16* Elp = g_El + (size_t)(b*NC + er) * HW;
    const __nv_bfloat16* Ahp = g_xh + (size_t)(b*NC + jh*64 + ar) * HW;
    const __nv_bfloat16* Alp = g_xl + (size_t)(b*NC + jh*64 + ar) * HW;

    auto stage = [&](int st, int kt) {
        const int kk0 = kbase + kt * 32;
        const uint32_t sb = sb_u32 + st * GD_STAGE * 2;
        #pragma unroll
        for (int q = 0; q < 2; q++) {
            const int sg = es + q;
            cp16(sb + (er*LDK + sg*8)*2,           Ehp + kk0 + sg*8);
            cp16(sb + (128*LDK + er*LDK + sg*8)*2, Elp + kk0 + sg*8);
        }
        cp16(sb + (2*128*LDK + ar*LDK + as_*8)*2,          Ahp + kk0 + as_*8);
        cp16(sb + (2*128*LDK + 64*LDK + ar*LDK + as_*8)*2, Alp + kk0 + as_*8);
        asm volatile("cp.async.commit_group;");
    };

    stage(0, 0);
    stage(1, 1);

    wmma::fragment<wmma::accumulator, 16, 16, 16, float> acc[2][2];
    #pragma unroll
    for (int mt = 0; mt < 2; mt++)
        #pragma unroll
        for (int nt = 0; nt < 2; nt++)
            wmma::fill_fragment(acc[mt][nt], 0.0f);

    #pragma unroll
    for (int kt = 0; kt < 8; kt++) {
        const int cur = kt & 1;
        if (kt == 7) asm volatile("cp.async.wait_group 0;" ::: "memory");
        else         asm volatile("cp.async.wait_group 1;" ::: "memory");
        __syncthreads();

        __nv_bfloat16* sEh = sbase + cur*GD_STAGE;
        __nv_bfloat16* sEl = sEh + 128*LDK;
        __nv_bfloat16* sAh = sEl + 128*LDK;
        __nv_bfloat16* sAl = sAh + 64*LDK;

        #pragma unroll
        for (int kk = 0; kk < 2; kk++) {
            wmma::fragment<wmma::matrix_a, 16, 16, 16, __nv_bfloat16, wmma::row_major> ah[2], al[2];
            #pragma unroll
            for (int mt = 0; mt < 2; mt++) {
                const int i0 = wi*32 + mt*16;
                wmma::load_matrix_sync(ah[mt], &sEh[i0*LDK + kk*16], LDK);
                wmma::load_matrix_sync(al[mt], &sEl[i0*LDK + kk*16], LDK);
            }
            #pragma unroll
            for (int nt = 0; nt < 2; nt++) {
                wmma::fragment<wmma::matrix_b, 16, 16, 16, __nv_bfloat16, wmma::col_major> bh, bl;
                const int j0 = wj*32 + nt*16;
                wmma::load_matrix_sync(bh, &sAh[j0*LDK + kk*16], LDK);
                wmma::load_matrix_sync(bl, &sAl[j0*LDK + kk*16], LDK);
                #pragma unroll
                for (int mt = 0; mt < 2; mt++) {
                    wmma::mma_sync(acc[mt][nt], ah[mt], bh, acc[mt][nt]);
                    wmma::mma_sync(acc[mt][nt], ah[mt], bl, acc[mt][nt]);
                    wmma::mma_sync(acc[mt][nt], al[mt], bh, acc[mt][nt]);
                }
            }
        }

        __syncthreads();
        if (kt < 6) stage(cur, kt + 2);
    }

    float* gp = g_gdp + ((size_t)s * NB + b) * NC * NC;
    #pragma unroll
    for (int mt = 0; mt < 2; mt++)
        #pragma unroll
        for (int nt = 0; nt < 2; nt++)
            wmma::store_matrix_sync(gp + (wi*32 + mt*16) * NC + jh*64 + wj*32 + nt*16,
                                    acc[mt][nt], NC, wmma::mem_row_major);
}

// ---------------------------------------------------------------------------
// Kernel S1: g_gds = sum over splits of gdp (fp32)  (R10: wide-parallel)
// ---------------------------------------------------------------------------
__global__ __launch_bounds__(256) void gdsum_kernel()
{
    const int idx = blockIdx.x * 256 + threadIdx.x;   // < NB*NC*NC
    float sum = 0.f;
    #pragma unroll
    for (int s = 0; s < KSPLIT; s++)
        sum += g_gdp[(size_t)s * (NB*NC*NC) + idx];
    g_gds[idx] = sum;
}

// ---------------------------------------------------------------------------
// Kernel S2: gd'^T[b][j][i] = (sum_c M[i][c] * wA[j][c]) * scl[i] + bA[j]*bscl[i]
// Exact fp32 GEMM per batch. grid 32 blocks, 256 threads (16x16), 8jx8i microtile.
// ---------------------------------------------------------------------------
#define LDR 132
#define GG_SMEM (2*128*LDR*4)

__global__ __launch_bounds__(256, 1) void gdgemm_kernel(
    const float* __restrict__ wA, const float* __restrict__ bA)
{
    extern __shared__ char smraw[];
    float* sM = (float*)smraw;          // [c][i]
    float* sW = sM + 128*LDR;           // [c][j]

    const int b = blockIdx.x, tid = threadIdx.x;
    const int tx = tid & 15, ty = tid >> 4;

    for (int idx = tid; idx < NC*NC; idx += 256) {
        const int r = idx >> 7, c = idx & 127;
        sM[c*LDR + r] = g_gds[b*NC*NC + idx];
        sW[c*LDR + r] = wA[idx];
    }
    __syncthreads();

    float acc[8][8];
    #pragma unroll
    for (int a = 0; a < 8; a++)
        #pragma unroll
        for (int d = 0; d < 8; d++) acc[a][d] = 0.f;

    for (int c = 0; c < 128; c++) {
        float4 j0 = *(const float4*)&sW[c*LDR + ty*8];
        float4 j1 = *(const float4*)&sW[c*LDR + ty*8 + 4];
        float4 i0 = *(const float4*)&sM[c*LDR + tx*8];
        float4 i1 = *(const float4*)&sM[c*LDR + tx*8 + 4];
        const float jv[8] = {j0.x, j0.y, j0.z, j0.w, j1.x, j1.y, j1.z, j1.w};
        const float iv[8] = {i0.x, i0.y, i0.z, i0.w, i1.x, i1.y, i1.z, i1.w};
        #pragma unroll
        for (int a = 0; a < 8; a++)
            #pragma unroll
            for (int d = 0; d < 8; d++)
                acc[a][d] += jv[a] * iv[d];
    }

    #pragma unroll
    for (int a = 0; a < 8; a++) {
        const int j = ty*8 + a;
        const float bAj = bA[j];
        #pragma unroll
        for (int d = 0; d < 8; d += 2) {
            const int i = tx*8 + d;
            const float v0 = acc[a][d]   * g_scl[b*NC + i]   + bAj * g_bscl[b*NC + i];
            const float v1 = acc[a][d+1] * g_scl[b*NC + i+1] + bAj * g_bscl[b*NC + i+1];
            __nv_bfloat16 h0, l0, h1, l1;
            split_bf16(v0, h0, l0);
            split_bf16(v1, h1, l1);
            const size_t t = (size_t)b*NC*NC + (size_t)j*NC + i;
            *(__nv_bfloat162*)&g_gTh[t] = __halves2bfloat162(h0, h1);
            *(__nv_bfloat162*)&g_gTl[t] = __halves2bfloat162(l0, l1);
        }
    }
}

// ---------------------------------------------------------------------------
// Kernel O: out[b,j,n] = sum_i F[i,n]*gd'[i,j]  (3-term bf16 GEMM, K=128)
// cp.async 3-STAGE pipeline, k-chunk 16. grid (HW/128, NB), 256 thr.
// smem: 3 x [Gh 128*LDW | Gl 128*LDW | Fh 16*LDA | Fl 16*LDA]  (~63 KB)
// ---------------------------------------------------------------------------
#define O_STAGE (2*128*LDW + 2*16*LDA)
#define OUT_SMEM (3*O_STAGE*2)

__global__ __launch_bounds__(256, 2) void out_wmma(float* __restrict__ out)
{
    extern __shared__ char smraw[];
    __nv_bfloat16* sbase = (__nv_bfloat16*)smraw;
    const uint32_t sb_u32 = smem_u32(smraw);

    const int tid = threadIdx.x, w = tid >> 5;
    const int b = blockIdx.y, n0 = blockIdx.x * 128;
    const int wm = w & 3, wn = w >> 2;

    const int hl = tid >> 7, gr = tid & 127;
    const __nv_bfloat16* gsrc = (hl ? g_gTl : g_gTh) + (size_t)(b*NC + gr) * NC;
    const int fq0 = (tid & 127) * 2;
    const __nv_bfloat16* fsrc = (hl ? g_Fl : g_Fh);

    auto stage = [&](int st, int kt) {
        const uint32_t sb = sb_u32 + st * O_STAGE * 2;
        const uint32_t gdst = sb + (hl*128*LDW + gr*LDW)*2;
        #pragma unroll
        for (int sg = 0; sg < 2; sg++)
            cp16(gdst + sg*16, gsrc + kt*16 + sg*8);
        const uint32_t fdst = sb + (2*128*LDW + hl*16*LDA)*2;
        #pragma unroll
        for (int q = 0; q < 2; q++) {
            const int idx = fq0 + q, row = idx >> 4, sg = idx & 15;
            cp16(fdst + (row*LDA + sg*8)*2,
                 fsrc + (size_t)(b*NC + kt*16 + row)*HW + n0 + sg*8);
        }
        asm volatile("cp.async.commit_group;");
    };

    stage(0, 0);
    stage(1, 1);
    stage(2, 2);

    wmma::fragment<wmma::accumulator, 16, 16, 16, float> acc[2][4];
    #pragma unroll
    for (int mt = 0; mt < 2; mt++)
        #pragma unroll
        for (int nt = 0; nt < 4; nt++)
            wmma::fill_fragment(acc[mt][nt], 0.0f);

    #pragma unroll
    for (int kt = 0; kt < 8; kt++) {
        const int cur = kt % 3;
        if (kt >= 7)      asm volatile("cp.async.wait_group 0;" ::: "memory");
        else if (kt >= 6) asm volatile("cp.async.wait_group 1;" ::: "memory");
        else              asm volatile("cp.async.wait_group 2;" ::: "memory");
        __syncthreads();

        __nv_bfloat16* bGh = sbase + cur*O_STAGE;
        __nv_bfloat16* bGl = bGh + 128*LDW;
        __nv_bfloat16* bFh = bGl + 128*LDW;
        __nv_bfloat16* bFl = bFh + 16*LDA;

        wmma::fragment<wmma::matrix_a, 16, 16, 16, __nv_bfloat16, wmma::row_major> ah[2], al[2];
        #pragma unroll
        for (int mt = 0; mt < 2; mt++) {
            const int j0 = wm*32 + mt*16;
            wmma::load_matrix_sync(ah[mt], &bGh[j0*LDW], LDW);
            wmma::load_matrix_sync(al[mt], &bGl[j0*LDW], LDW);
        }
        #pragma unroll
        for (int nt = 0; nt < 4; nt++) {
            wmma::fragment<wmma::matrix_b, 16, 16, 16, __nv_bfloat16, wmma::row_major> bh, bl;
            const int c0 = wn*64 + nt*16;
            wmma::load_matrix_sync(bh, &bFh[c0], LDA);
            wmma::load_matrix_sync(bl, &bFl[c0], LDA);
            #pragma unroll
            for (int mt = 0; mt < 2; mt++) {
                wmma::mma_sync(acc[mt][nt], ah[mt], bh, acc[mt][nt]);
                wmma::mma_sync(acc[mt][nt], ah[mt], bl, acc[mt][nt]);
                wmma::mma_sync(acc[mt][nt], al[mt], bh, acc[mt][nt]);
            }
        }

        __syncthreads();
        if (kt < 5) stage(cur, kt + 3);
    }

    #pragma unroll
    for (int mt = 0; mt < 2; mt++)
        #pragma unroll
        for (int nt = 0; nt < 4; nt++) {
            float* gp = out + ((size_t)b * NC + wm*32 + mt*16) * HW + n0 + wn*64 + nt*16;
            wmma::store_matrix_sync(gp, acc[mt][nt], HW, wmma::mem_row_major);
        }
}

// ---------------------------------------------------------------------------
extern "C" void kernel_launch(void* const* d_in, const int* in_sizes, int n_in,
                              void* d_out, int out_size)
{
    const float* x  = (const float*)d_in[0];
    const float* wA = (const float*)d_in[1];
    const float* bA = (const float*)d_in[2];
    const float* wB = (const float*)d_in[3];
    const float* bB = (const float*)d_in[4];  // unused: softmax shift-invariant
    const float* wV = (const float*)d_in[5];
    const float* bV = (const float*)d_in[6];  // unused: softmax shift-invariant
    (void)bB; (void)bV;
    float* out = (float*)d_out;

    cudaFuncSetAttribute(proj_wmma,    cudaFuncAttributeMaxDynamicSharedMemorySize, PROJ_SMEM);
    cudaFuncSetAttribute(gd_wmma,      cudaFuncAttributeMaxDynamicSharedMemorySize, GD_SMEM);
    cudaFuncSetAttribute(gdgemm_kernel,cudaFuncAttributeMaxDynamicSharedMemorySize, GG_SMEM);
    cudaFuncSetAttribute(out_wmma,     cudaFuncAttributeMaxDynamicSharedMemorySize, OUT_SMEM);

    wconv_kernel <<<2, 256>>>(wB, wV);
    xconv_kernel <<<(NB*NC*HW)/1024, 256>>>(x);
    proj_wmma    <<<dim3(HW/128, NB, 2), 256, PROJ_SMEM>>>();
    zfin_kernel  <<<NROW/256, 256>>>();
    gd_wmma      <<<dim3(KSPLIT, NB, 2), 256, GD_SMEM>>>();
    gdsum_kernel <<<(NB*NC*NC)/256, 256>>>();
    gdgemm_kernel<<<NB, 256, GG_SMEM>>>(wA, bA);
    out_wmma     <<<dim3(HW/128, NB), 256, OUT_SMEM>>>(out);
}

// round 16
// speedup vs baseline: 1.3803x; 1.0135x over previous
#include <cuda_runtime.h>
#include <cuda_bf16.h>
#include <mma.h>
#include <cstdint>

using namespace nvcuda;

#define NB 32
#define NC 128
#define HW 4096
#define NROW (NB*NC)
#define KSPLIT 16

#define LDA 136   // padded ld for 128-wide bf16 rows (272B -> conflict-free)
#define LDW 24    // padded ld for 16-wide bf16 k-chunks
#define LDK 40    // padded ld for 32-wide bf16 k-chunks (80B rows)

// Scratch (device globals: allocation-free kernel_launch)
__device__ __align__(16) __nv_bfloat16 g_xh[NB*NC*HW], g_xl[NB*NC*HW];   // x pair
__device__ __align__(16) __nv_bfloat16 g_Eh[NB*NC*HW], g_El[NB*NC*HW];   // exp(B)
__device__ __align__(16) __nv_bfloat16 g_Fh[NB*NC*HW], g_Fl[NB*NC*HW];   // exp(V)
__device__ float g_gdp[KSPLIT*NB*NC*NC];          // partials of M = E @ x^T
__device__ float g_gds[NB*NC*NC];                 // M summed over splits
__device__ __align__(16) __nv_bfloat16 g_gTh[NB*NC*NC];   // gd'^T [b][j][i]
__device__ __align__(16) __nv_bfloat16 g_gTl[NB*NC*NC];
__device__ float g_zBp[32*NROW], g_zVp[32*NROW];
__device__ float g_scl[NROW], g_bscl[NROW];       // 1/(zB*HW*zV), 1/(HW*zV)
__device__ __align__(16) __nv_bfloat16 g_wh[2*NC*NC], g_wl[2*NC*NC];  // wB, wV pairs

__device__ __forceinline__ void split_bf16(float f, __nv_bfloat16& h, __nv_bfloat16& l) {
    h = __float2bfloat16(f);
    l = __float2bfloat16(f - __bfloat162float(h));
}
__device__ __forceinline__ void cp16(uint32_t saddr, const void* g) {
    asm volatile("cp.async.ca.shared.global [%0], [%1], 16;" :: "r"(saddr), "l"(g));
}
__device__ __forceinline__ uint32_t smem_u32(const void* p) {
    uint32_t a;
    asm("{ .reg .u64 t; cvta.to.shared.u64 t, %1; cvt.u32.u64 %0, t; }" : "=r"(a) : "l"(p));
    return a;
}

// ---------------------------------------------------------------------------
// Kernel W: wB, wV -> bf16 hi/lo (wA stays fp32; used exactly in gdgemm)
// ---------------------------------------------------------------------------
__global__ __launch_bounds__(256) void wconv_kernel(
    const float* __restrict__ wB, const float* __restrict__ wV)
{
    const float* ws[2] = {wB, wV};
    const int m = blockIdx.x;
    const float* w = ws[m];
    for (int idx = threadIdx.x; idx < NC*NC; idx += 256) {
        __nv_bfloat16 h, l;
        split_bf16(w[idx], h, l);
        g_wh[m*NC*NC + idx] = h;
        g_wl[m*NC*NC + idx] = l;
    }
}

// ---------------------------------------------------------------------------
// Kernel X: x fp32 -> bf16 hi/lo pair (one-time)
// ---------------------------------------------------------------------------
__global__ __launch_bounds__(256) void xconv_kernel(const float* __restrict__ x)
{
    const size_t i0 = ((size_t)blockIdx.x * 256 + threadIdx.x) * 4;
    float4 v = *(const float4*)(x + i0);
    __nv_bfloat16 h0, l0, h1, l1, h2, l2, h3, l3;
    split_bf16(v.x, h0, l0);
    split_bf16(v.y, h1, l1);
    split_bf16(v.z, h2, l2);
    split_bf16(v.w, h3, l3);
    *(__nv_bfloat162*)&g_xh[i0]     = __halves2bfloat162(h0, h1);
    *(__nv_bfloat162*)&g_xh[i0 + 2] = __halves2bfloat162(h2, h3);
    *(__nv_bfloat162*)&g_xl[i0]     = __halves2bfloat162(l0, l1);
    *(__nv_bfloat162*)&g_xl[i0 + 2] = __halves2bfloat162(l2, l3);
}

// ---------------------------------------------------------------------------
// Kernel P: E/F projections (m = blockIdx.z: 0 -> exp(wB x), 1 -> exp(wV x)).
// 3-term split. W(pair) + X(pair) streamed via cp.async 2-stage pipeline.
// block 128o x 128n, warp 32x64, 256 thr, 2 blk/SM.  (R10 config)
// ---------------------------------------------------------------------------
#define P_STAGE (2*128*LDK + 2*32*LDA)
#define PROJ_SMEM (2*P_STAGE*2 + 8*16*20*4 + 128*4*4)

__global__ __launch_bounds__(256, 2) void proj_wmma()
{
    extern __shared__ char smraw[];
    __nv_bfloat16* sbase = (__nv_bfloat16*)smraw;
    const uint32_t sb_u32 = smem_u32(smraw);
    float* stage = (float*)(sbase + 2*P_STAGE);       // 8 warps x 16x20
    float* zsm   = stage + 8*16*20;                   // [128][4]

    const int tid = threadIdx.x, w = tid >> 5, lane = tid & 31;
    const int b = blockIdx.y, n0 = blockIdx.x * 128;
    const int m = blockIdx.z;
    const int wm = w & 3, wn = w >> 2;

    const int whl = tid >> 7, wr = tid & 127;
    const int xq0 = (tid & 127) * 4;
    const __nv_bfloat16* xsrc = (whl ? g_xl : g_xh);
    const __nv_bfloat16* wsrc0 = (whl ? g_wl : g_wh) + m*NC*NC + wr*NC;

    auto stage_cp = [&](int st, int kt) {
        const uint32_t sb = sb_u32 + st * P_STAGE * 2;
        const __nv_bfloat16* wsrc = wsrc0 + kt*32;
        const uint32_t wdst = sb + (whl*128*LDK + wr*LDK)*2;
        #pragma unroll
        for (int sg = 0; sg < 4; sg++)
            cp16(wdst + sg*16, wsrc + sg*8);
        const uint32_t xdst = sb + (2*128*LDK + whl*32*LDA)*2;
        #pragma unroll
        for (int q = 0; q < 4; q++) {
            const int idx = xq0 + q, row = idx >> 4, sg = idx & 15;
            cp16(xdst + (row*LDA + sg*8)*2,
                 xsrc + ((size_t)(b*NC + kt*32 + row))*HW + n0 + sg*8);
        }
        asm volatile("cp.async.commit_group;");
    };

    stage_cp(0, 0);
    stage_cp(1, 1);

    wmma::fragment<wmma::accumulator, 16, 16, 16, float> acc[2][4];
    #pragma unroll
    for (int mt = 0; mt < 2; mt++)
        #pragma unroll
        for (int nt = 0; nt < 4; nt++)
            wmma::fill_fragment(acc[mt][nt], 0.0f);

    #pragma unroll
    for (int kt = 0; kt < 4; kt++) {
        const int cur = kt & 1;
        if (kt == 3) asm volatile("cp.async.wait_group 0;" ::: "memory");
        else         asm volatile("cp.async.wait_group 1;" ::: "memory");
        __syncthreads();

        __nv_bfloat16* sWh = sbase + cur*P_STAGE;
        __nv_bfloat16* sWl = sWh + 128*LDK;
        __nv_bfloat16* sXh = sWl + 128*LDK;
        __nv_bfloat16* sXl = sXh + 32*LDA;

        #pragma unroll
        for (int kk = 0; kk < 2; kk++) {
            wmma::fragment<wmma::matrix_a, 16, 16, 16, __nv_bfloat16, wmma::row_major> ah[2], al[2];
            #pragma unroll
            for (int mt = 0; mt < 2; mt++) {
                const int o0 = wm*32 + mt*16;
                wmma::load_matrix_sync(ah[mt], &sWh[o0*LDK + kk*16], LDK);
                wmma::load_matrix_sync(al[mt], &sWl[o0*LDK + kk*16], LDK);
            }
            #pragma unroll
            for (int nt = 0; nt < 4; nt++) {
                wmma::fragment<wmma::matrix_b, 16, 16, 16, __nv_bfloat16, wmma::row_major> bh, bl;
                const int c0 = wn*64 + nt*16;
                wmma::load_matrix_sync(bh, &sXh[kk*16*LDA + c0], LDA);
                wmma::load_matrix_sync(bl, &sXl[kk*16*LDA + c0], LDA);
                #pragma unroll
                for (int mt = 0; mt < 2; mt++) {
                    wmma::mma_sync(acc[mt][nt], ah[mt], bh, acc[mt][nt]);
                    wmma::mma_sync(acc[mt][nt], ah[mt], bl, acc[mt][nt]);
                    wmma::mma_sync(acc[mt][nt], al[mt], bh, acc[mt][nt]);
                }
            }
        }

        __syncthreads();
        if (kt < 2) stage_cp(cur, kt + 2);
    }

    // Epilogue: exp, split, store pair + row partial sums
    float* st = stage + w * 16 * 20;
    float rs0 = 0.f, rs1 = 0.f;
    __nv_bfloat16* dh = (m == 0) ? g_Eh : g_Fh;
    __nv_bfloat16* dl = (m == 0) ? g_El : g_Fl;
    #pragma unroll
    for (int mt = 0; mt < 2; mt++)
        #pragma unroll
        for (int nt = 0; nt < 4; nt++) {
            wmma::store_matrix_sync(st, acc[mt][nt], 20, wmma::mem_row_major);
            __syncwarp();
            const int r = lane & 15, c8 = (lane >> 4) * 8;
            const int o = wm*32 + mt*16 + r;
            const int nn = n0 + wn*64 + nt*16 + c8;
            const float* sp = st + r*20 + c8;
            const size_t gb = ((size_t)b * NC + o) * HW + nn;
            float v[8];
            float lsum = 0.f;
            #pragma unroll
            for (int k = 0; k < 8; k++) { v[k] = __expf(sp[k]); lsum += v[k]; }
            if (mt == 0) rs0 += lsum; else rs1 += lsum;
            #pragma unroll
            for (int k = 0; k < 8; k += 2) {
                __nv_bfloat16 h0, l0, h1, l1;
                split_bf16(v[k],   h0, l0);
                split_bf16(v[k+1], h1, l1);
                *(__nv_bfloat162*)&dh[gb + k] = __halves2bfloat162(h0, h1);
                *(__nv_bfloat162*)&dl[gb + k] = __halves2bfloat162(l0, l1);
            }
            __syncwarp();
        }

    {
        const int idx = wn*2 + (lane >> 4), r = lane & 15;
        zsm[(wm*32 + r)*4 + idx]      = rs0;
        zsm[(wm*32 + 16 + r)*4 + idx] = rs1;
        __syncthreads();
        if (tid < 128) {
            float z = zsm[tid*4] + zsm[tid*4+1] + zsm[tid*4+2] + zsm[tid*4+3];
            float* zp = (m == 0) ? g_zBp : g_zVp;
            zp[blockIdx.x*NROW + b*NC + tid] = z;
        }
    }
}

// ---------------------------------------------------------------------------
// Kernel Z: finalize per-row scales (deterministic sum of 32 partials)
// ---------------------------------------------------------------------------
__global__ __launch_bounds__(256) void zfin_kernel()
{
    const int row = blockIdx.x * 256 + threadIdx.x;   // < NROW
    float zb = 0.f, zv = 0.f;
    #pragma unroll
    for (int nb = 0; nb < 32; nb++) {
        zb += g_zBp[nb*NROW + row];
        zv += g_zVp[nb*NROW + row];
    }
    g_scl[row]  = 1.0f / (zb * (float)HW * zv);
    g_bscl[row] = 1.0f / ((float)HW * zv);
}

// ---------------------------------------------------------------------------
// Kernel G: M partials: gdp[s][b][i][c] = sum_{n in 256-chunk} E[i,n]*x[c,n]
// NEW: block 128i x 128c (no jh split -> E staged once), warp 32i x 64c,
// 256 thr, 2 blk/SM. cp.async 2-stage, k-chunk 32.
// stage (elems): [Eh 128*LDK][El 128*LDK][Xh 128*LDK][Xl 128*LDK] = 20480
// ---------------------------------------------------------------------------
#define GD_STAGE (4*128*LDK)
#define GD_SMEM  (2*GD_STAGE*2)

__global__ __launch_bounds__(256, 2) void gd_wmma()
{
    extern __shared__ char smraw[];
    __nv_bfloat16* sbase = (__nv_bfloat16*)smraw;
    const uint32_t sb_u32 = smem_u32(smraw);

    const int tid = threadIdx.x, w = tid >> 5;
    const int s = blockIdx.x, b = blockIdx.y;
    const int kbase = s * 256;
    const int wi = w & 3, wc = w >> 2;

    // staging: each thread 8 cp16 (Eh,El,Xh,Xl: row tid>>1, segs (tid&1)*2..+1)
    const int er = tid >> 1, es = (tid & 1) * 2;
    const __nv_bfloat16* Ehp = g_Eh + (size_t)(b*NC + er) * HW;
    const __nv_bfloat16* Elp = g_El + (size_t)(b*NC + er) * HW;
    const __nv_bfloat16* Xhp = g_xh + (size_t)(b*NC + er) * HW;
    const __nv_bfloat16* Xlp = g_xl + (size_t)(b*NC + er) * HW;

    auto stage = [&](int st, int kt) {
        const int kk0 = kbase + kt * 32;
        const uint32_t sb = sb_u32 + st * GD_STAGE * 2;
        #pragma unroll
        for (int q = 0; q < 2; q++) {
            const int sg = es + q;
            cp16(sb + (er*LDK + sg*8)*2,             Ehp + kk0 + sg*8);
            cp16(sb + (128*LDK + er*LDK + sg*8)*2,   Elp + kk0 + sg*8);
            cp16(sb + (2*128*LDK + er*LDK + sg*8)*2, Xhp + kk0 + sg*8);
            cp16(sb + (3*128*LDK + er*LDK + sg*8)*2, Xlp + kk0 + sg*8);
        }
        asm volatile("cp.async.commit_group;");
    };

    stage(0, 0);
    stage(1, 1);

    wmma::fragment<wmma::accumulator, 16, 16, 16, float> acc[2][4];
    #pragma unroll
    for (int mt = 0; mt < 2; mt++)
        #pragma unroll
        for (int nt = 0; nt < 4; nt++)
            wmma::fill_fragment(acc[mt][nt], 0.0f);

    #pragma unroll
    for (int kt = 0; kt < 8; kt++) {
        const int cur = kt & 1;
        if (kt == 7) asm volatile("cp.async.wait_group 0;" ::: "memory");
        else         asm volatile("cp.async.wait_group 1;" ::: "memory");
        __syncthreads();

        __nv_bfloat16* sEh = sbase + cur*GD_STAGE;
        __nv_bfloat16* sEl = sEh + 128*LDK;
        __nv_bfloat16* sXh = sEl + 128*LDK;
        __nv_bfloat16* sXl = sXh + 128*LDK;

        #pragma unroll
        for (int kk = 0; kk < 2; kk++) {
            wmma::fragment<wmma::matrix_a, 16, 16, 16, __nv_bfloat16, wmma::row_major> ah[2], al[2];
            #pragma unroll
            for (int mt = 0; mt < 2; mt++) {
                const int i0 = wi*32 + mt*16;
                wmma::load_matrix_sync(ah[mt], &sEh[i0*LDK + kk*16], LDK);
                wmma::load_matrix_sync(al[mt], &sEl[i0*LDK + kk*16], LDK);
            }
            #pragma unroll
            for (int nt = 0; nt < 4; nt++) {
                wmma::fragment<wmma::matrix_b, 16, 16, 16, __nv_bfloat16, wmma::col_major> bh, bl;
                const int c0 = wc*64 + nt*16;
                wmma::load_matrix_sync(bh, &sXh[c0*LDK + kk*16], LDK);
                wmma::load_matrix_sync(bl, &sXl[c0*LDK + kk*16], LDK);
                #pragma unroll
                for (int mt = 0; mt < 2; mt++) {
                    wmma::mma_sync(acc[mt][nt], ah[mt], bh, acc[mt][nt]);
                    wmma::mma_sync(acc[mt][nt], ah[mt], bl, acc[mt][nt]);
                    wmma::mma_sync(acc[mt][nt], al[mt], bh, acc[mt][nt]);
                }
            }
        }

        __syncthreads();
        if (kt < 6) stage(cur, kt + 2);
    }

    float* gp = g_gdp + ((size_t)s * NB + b) * NC * NC;
    #pragma unroll
    for (int mt = 0; mt < 2; mt++)
        #pragma unroll
        for (int nt = 0; nt < 4; nt++)
            wmma::store_matrix_sync(gp + (wi*32 + mt*16) * NC + wc*64 + nt*16,
                                    acc[mt][nt], NC, wmma::mem_row_major);
}

// ---------------------------------------------------------------------------
// Kernel S1: g_gds = sum over splits of gdp (fp32)  (wide-parallel)
// ---------------------------------------------------------------------------
__global__ __launch_bounds__(256) void gdsum_kernel()
{
    const int idx = blockIdx.x * 256 + threadIdx.x;   // < NB*NC*NC
    float sum = 0.f;
    #pragma unroll
    for (int s = 0; s < KSPLIT; s++)
        sum += g_gdp[(size_t)s * (NB*NC*NC) + idx];
    g_gds[idx] = sum;
}

// ---------------------------------------------------------------------------
// Kernel S2: gd'^T[b][j][i] = (sum_c M[i][c] * wA[j][c]) * scl[i] + bA[j]*bscl[i]
// Exact fp32 GEMM per batch. grid 32 blocks, 256 threads (16x16), 8jx8i microtile.
// ---------------------------------------------------------------------------
#define LDR 132
#define GG_SMEM (2*128*LDR*4)

__global__ __launch_bounds__(256, 1) void gdgemm_kernel(
    const float* __restrict__ wA, const float* __restrict__ bA)
{
    extern __shared__ char smraw[];
    float* sM = (float*)smraw;          // [c][i]
    float* sW = sM + 128*LDR;           // [c][j]

    const int b = blockIdx.x, tid = threadIdx.x;
    const int tx = tid & 15, ty = tid >> 4;

    for (int idx = tid; idx < NC*NC; idx += 256) {
        const int r = idx >> 7, c = idx & 127;
        sM[c*LDR + r] = g_gds[b*NC*NC + idx];
        sW[c*LDR + r] = wA[idx];
    }
    __syncthreads();

    float acc[8][8];
    #pragma unroll
    for (int a = 0; a < 8; a++)
        #pragma unroll
        for (int d = 0; d < 8; d++) acc[a][d] = 0.f;

    for (int c = 0; c < 128; c++) {
        float4 j0 = *(const float4*)&sW[c*LDR + ty*8];
        float4 j1 = *(const float4*)&sW[c*LDR + ty*8 + 4];
        float4 i0 = *(const float4*)&sM[c*LDR + tx*8];
        float4 i1 = *(const float4*)&sM[c*LDR + tx*8 + 4];
        const float jv[8] = {j0.x, j0.y, j0.z, j0.w, j1.x, j1.y, j1.z, j1.w};
        const float iv[8] = {i0.x, i0.y, i0.z, i0.w, i1.x, i1.y, i1.z, i1.w};
        #pragma unroll
        for (int a = 0; a < 8; a++)
            #pragma unroll
            for (int d = 0; d < 8; d++)
                acc[a][d] += jv[a] * iv[d];
    }

    #pragma unroll
    for (int a = 0; a < 8; a++) {
        const int j = ty*8 + a;
        const float bAj = bA[j];
        #pragma unroll
        for (int d = 0; d < 8; d += 2) {
            const int i = tx*8 + d;
            const float v0 = acc[a][d]   * g_scl[b*NC + i]   + bAj * g_bscl[b*NC + i];
            const float v1 = acc[a][d+1] * g_scl[b*NC + i+1] + bAj * g_bscl[b*NC + i+1];
            __nv_bfloat16 h0, l0, h1, l1;
            split_bf16(v0, h0, l0);
            split_bf16(v1, h1, l1);
            const size_t t = (size_t)b*NC*NC + (size_t)j*NC + i;
            *(__nv_bfloat162*)&g_gTh[t] = __halves2bfloat162(h0, h1);
            *(__nv_bfloat162*)&g_gTl[t] = __halves2bfloat162(l0, l1);
        }
    }
}

// ---------------------------------------------------------------------------
// Kernel O: out[b,j,n] = sum_i F[i,n]*gd'[i,j]  (3-term bf16 GEMM, K=128)
// cp.async 3-stage, k-chunk 16. grid (HW/128, NB), 256 thr.  (R15 config)
// ---------------------------------------------------------------------------
#define O_STAGE (2*128*LDW + 2*16*LDA)
#define OUT_SMEM (3*O_STAGE*2)

__global__ __launch_bounds__(256, 2) void out_wmma(float* __restrict__ out)
{
    extern __shared__ char smraw[];
    __nv_bfloat16* sbase = (__nv_bfloat16*)smraw;
    const uint32_t sb_u32 = smem_u32(smraw);

    const int tid = threadIdx.x, w = tid >> 5;
    const int b = blockIdx.y, n0 = blockIdx.x * 128;
    const int wm = w & 3, wn = w >> 2;

    const int hl = tid >> 7, gr = tid & 127;
    const __nv_bfloat16* gsrc = (hl ? g_gTl : g_gTh) + (size_t)(b*NC + gr) * NC;
    const int fq0 = (tid & 127) * 2;
    const __nv_bfloat16* fsrc = (hl ? g_Fl : g_Fh);

    auto stage = [&](int st, int kt) {
        const uint32_t sb = sb_u32 + st * O_STAGE * 2;
        const uint32_t gdst = sb + (hl*128*LDW + gr*LDW)*2;
        #pragma unroll
        for (int sg = 0; sg < 2; sg++)
            cp16(gdst + sg*16, gsrc + kt*16 + sg*8);
        const uint32_t fdst = sb + (2*128*LDW + hl*16*LDA)*2;
        #pragma unroll
        for (int q = 0; q < 2; q++) {
            const int idx = fq0 + q, row = idx >> 4, sg = idx & 15;
            cp16(fdst + (row*LDA + sg*8)*2,
                 fsrc + (size_t)(b*NC + kt*16 + row)*HW + n0 + sg*8);
        }
        asm volatile("cp.async.commit_group;");
    };

    stage(0, 0);
    stage(1, 1);
    stage(2, 2);

    wmma::fragment<wmma::accumulator, 16, 16, 16, float> acc[2][4];
    #pragma unroll
    for (int mt = 0; mt < 2; mt++)
        #pragma unroll
        for (int nt = 0; nt < 4; nt++)
            wmma::fill_fragment(acc[mt][nt], 0.0f);

    #pragma unroll
    for (int kt = 0; kt < 8; kt++) {
        const int cur = kt % 3;
        if (kt >= 7)      asm volatile("cp.async.wait_group 0;" ::: "memory");
        else if (kt >= 6) asm volatile("cp.async.wait_group 1;" ::: "memory");
        else              asm volatile("cp.async.wait_group 2;" ::: "memory");
        __syncthreads();

        __nv_bfloat16* bGh = sbase + cur*O_STAGE;
        __nv_bfloat16* bGl = bGh + 128*LDW;
        __nv_bfloat16* bFh = bGl + 128*LDW;
        __nv_bfloat16* bFl = bFh + 16*LDA;

        wmma::fragment<wmma::matrix_a, 16, 16, 16, __nv_bfloat16, wmma::row_major> ah[2], al[2];
        #pragma unroll
        for (int mt = 0; mt < 2; mt++) {
            const int j0 = wm*32 + mt*16;
            wmma::load_matrix_sync(ah[mt], &bGh[j0*LDW], LDW);
            wmma::load_matrix_sync(al[mt], &bGl[j0*LDW], LDW);
        }
        #pragma unroll
        for (int nt = 0; nt < 4; nt++) {
            wmma::fragment<wmma::matrix_b, 16, 16, 16, __nv_bfloat16, wmma::row_major> bh, bl;
            const int c0 = wn*64 + nt*16;
            wmma::load_matrix_sync(bh, &bFh[c0], LDA);
            wmma::load_matrix_sync(bl, &bFl[c0], LDA);
            #pragma unroll
            for (int mt = 0; mt < 2; mt++) {
                wmma::mma_sync(acc[mt][nt], ah[mt], bh, acc[mt][nt]);
                wmma::mma_sync(acc[mt][nt], ah[mt], bl, acc[mt][nt]);
                wmma::mma_sync(acc[mt][nt], al[mt], bh, acc[mt][nt]);
            }
        }

        __syncthreads();
        if (kt < 5) stage(cur, kt + 3);
    }

    #pragma unroll
    for (int mt = 0; mt < 2; mt++)
        #pragma unroll
        for (int nt = 0; nt < 4; nt++) {
            float* gp = out + ((size_t)b * NC + wm*32 + mt*16) * HW + n0 + wn*64 + nt*16;
            wmma::store_matrix_sync(gp, acc[mt][nt], HW, wmma::mem_row_major);
        }
}

// ---------------------------------------------------------------------------
extern "C" void kernel_launch(void* const* d_in, const int* in_sizes, int n_in,
                              void* d_out, int out_size)
{
    const float* x  = (const float*)d_in[0];
    const float* wA = (const float*)d_in[1];
    const float* bA = (const float*)d_in[2];
    const float* wB = (const float*)d_in[3];
    const float* bB = (const float*)d_in[4];  // unused: softmax shift-invariant
    const float* wV = (const float*)d_in[5];
    const float* bV = (const float*)d_in[6];  // unused: softmax shift-invariant
    (void)bB; (void)bV;
    float* out = (float*)d_out;

    cudaFuncSetAttribute(proj_wmma,    cudaFuncAttributeMaxDynamicSharedMemorySize, PROJ_SMEM);
    cudaFuncSetAttribute(gd_wmma,      cudaFuncAttributeMaxDynamicSharedMemorySize, GD_SMEM);
    cudaFuncSetAttribute(gdgemm_kernel,cudaFuncAttributeMaxDynamicSharedMemorySize, GG_SMEM);
    cudaFuncSetAttribute(out_wmma,     cudaFuncAttributeMaxDynamicSharedMemorySize, OUT_SMEM);

    wconv_kernel <<<2, 256>>>(wB, wV);
    xconv_kernel <<<(NB*NC*HW)/1024, 256>>>(x);
    proj_wmma    <<<dim3(HW/128, NB, 2), 256, PROJ_SMEM>>>();
    zfin_kernel  <<<NROW/256, 256>>>();
    gd_wmma      <<<dim3(KSPLIT, NB), 256, GD_SMEM>>>();
    gdsum_kernel <<<(NB*NC*NC)/256, 256>>>();
    gdgemm_kernel<<<NB, 256, GG_SMEM>>>(wA, bA);
    out_wmma     <<<dim3(HW/128, NB), 256, OUT_SMEM>>>(out);
}

// round 17
// speedup vs baseline: 1.3911x; 1.0078x over previous
#include <cuda_runtime.h>
#include <cuda_bf16.h>
#include <mma.h>
#include <cstdint>

using namespace nvcuda;

#define NB 32
#define NC 128
#define HW 4096
#define NROW (NB*NC)
#define KSPLIT 8

#define LDA 136   // padded ld for 128-wide bf16 rows (272B -> conflict-free)
#define LDK 40    // padded ld for 32-wide bf16 k-chunks (80B rows)

// Scratch (device globals: allocation-free kernel_launch)
__device__ __align__(16) __nv_bfloat16 g_xh[NB*NC*HW], g_xl[NB*NC*HW];   // x pair
__device__ __align__(16) __nv_bfloat16 g_Eh[NB*NC*HW], g_El[NB*NC*HW];   // exp(B)
__device__ __align__(16) __nv_bfloat16 g_Fh[NB*NC*HW], g_Fl[NB*NC*HW];   // exp(V)
__device__ float g_gdp[KSPLIT*NB*NC*NC];          // partials of M = E @ x^T
__device__ float g_gds[NB*NC*NC];                 // M summed over splits
__device__ __align__(16) __nv_bfloat16 g_gTh[NB*NC*NC];   // gd'^T [b][j][i]
__device__ __align__(16) __nv_bfloat16 g_gTl[NB*NC*NC];
__device__ float g_zBp[32*NROW], g_zVp[32*NROW];
__device__ __align__(16) __nv_bfloat16 g_wh[2*NC*NC], g_wl[2*NC*NC];  // wB, wV pairs

__device__ __forceinline__ void split_bf16(float f, __nv_bfloat16& h, __nv_bfloat16& l) {
    h = __float2bfloat16(f);
    l = __float2bfloat16(f - __bfloat162float(h));
}
__device__ __forceinline__ void cp16(uint32_t saddr, const void* g) {
    asm volatile("cp.async.ca.shared.global [%0], [%1], 16;" :: "r"(saddr), "l"(g));
}
__device__ __forceinline__ uint32_t smem_u32(const void* p) {
    uint32_t a;
    asm("{ .reg .u64 t; cvta.to.shared.u64 t, %1; cvt.u32.u64 %0, t; }" : "=r"(a) : "l"(p));
    return a;
}

// ---------------------------------------------------------------------------
// Kernel W: wB, wV -> bf16 hi/lo (wA stays fp32; used exactly in gdgemm)
// ---------------------------------------------------------------------------
__global__ __launch_bounds__(256) void wconv_kernel(
    const float* __restrict__ wB, const float* __restrict__ wV)
{
    const float* ws[2] = {wB, wV};
    const int m = blockIdx.x;
    const float* w = ws[m];
    for (int idx = threadIdx.x; idx < NC*NC; idx += 256) {
        __nv_bfloat16 h, l;
        split_bf16(w[idx], h, l);
        g_wh[m*NC*NC + idx] = h;
        g_wl[m*NC*NC + idx] = l;
    }
}

// ---------------------------------------------------------------------------
// Kernel X: x fp32 -> bf16 hi/lo pair (one-time)
// ---------------------------------------------------------------------------
__global__ __launch_bounds__(256) void xconv_kernel(const float* __restrict__ x)
{
    const size_t i0 = ((size_t)blockIdx.x * 256 + threadIdx.x) * 4;
    float4 v = *(const float4*)(x + i0);
    __nv_bfloat16 h0, l0, h1, l1, h2, l2, h3, l3;
    split_bf16(v.x, h0, l0);
    split_bf16(v.y, h1, l1);
    split_bf16(v.z, h2, l2);
    split_bf16(v.w, h3, l3);
    *(__nv_bfloat162*)&g_xh[i0]     = __halves2bfloat162(h0, h1);
    *(__nv_bfloat162*)&g_xh[i0 + 2] = __halves2bfloat162(h2, h3);
    *(__nv_bfloat162*)&g_xl[i0]     = __halves2bfloat162(l0, l1);
    *(__nv_bfloat162*)&g_xl[i0 + 2] = __halves2bfloat162(l2, l3);
}

// ---------------------------------------------------------------------------
// Kernel P: E/F projections (m = blockIdx.z: 0 -> exp(wB x), 1 -> exp(wV x)).
// 3-term split. W(pair) + X(pair) streamed via cp.async 2-stage pipeline.
// block 128o x 128n, warp 32x64, 256 thr, 2 blk/SM.  (R10 config)
// ---------------------------------------------------------------------------
#define P_STAGE (2*128*LDK + 2*32*LDA)
#define PROJ_SMEM (2*P_STAGE*2 + 8*16*20*4 + 128*4*4)

__global__ __launch_bounds__(256, 2) void proj_wmma()
{
    extern __shared__ char smraw[];
    __nv_bfloat16* sbase = (__nv_bfloat16*)smraw;
    const uint32_t sb_u32 = smem_u32(smraw);
    float* stage = (float*)(sbase + 2*P_STAGE);       // 8 warps x 16x20
    float* zsm   = stage + 8*16*20;                   // [128][4]

    const int tid = threadIdx.x, w = tid >> 5, lane = tid & 31;
    const int b = blockIdx.y, n0 = blockIdx.x * 128;
    const int m = blockIdx.z;
    const int wm = w & 3, wn = w >> 2;

    const int whl = tid >> 7, wr = tid & 127;
    const int xq0 = (tid & 127) * 4;
    const __nv_bfloat16* xsrc = (whl ? g_xl : g_xh);
    const __nv_bfloat16* wsrc0 = (whl ? g_wl : g_wh) + m*NC*NC + wr*NC;

    auto stage_cp = [&](int st, int kt) {
        const uint32_t sb = sb_u32 + st * P_STAGE * 2;
        const __nv_bfloat16* wsrc = wsrc0 + kt*32;
        const uint32_t wdst = sb + (whl*128*LDK + wr*LDK)*2;
        #pragma unroll
        for (int sg = 0; sg < 4; sg++)
            cp16(wdst + sg*16, wsrc + sg*8);
        const uint32_t xdst = sb + (2*128*LDK + whl*32*LDA)*2;
        #pragma unroll
        for (int q = 0; q < 4; q++) {
            const int idx = xq0 + q, row = idx >> 4, sg = idx & 15;
            cp16(xdst + (row*LDA + sg*8)*2,
                 xsrc + ((size_t)(b*NC + kt*32 + row))*HW + n0 + sg*8);
        }
        asm volatile("cp.async.commit_group;");
    };

    stage_cp(0, 0);
    stage_cp(1, 1);

    wmma::fragment<wmma::accumulator, 16, 16, 16, float> acc[2][4];
    #pragma unroll
    for (int mt = 0; mt < 2; mt++)
        #pragma unroll
        for (int nt = 0; nt < 4; nt++)
            wmma::fill_fragment(acc[mt][nt], 0.0f);

    #pragma unroll
    for (int kt = 0; kt < 4; kt++) {
        const int cur = kt & 1;
        if (kt == 3) asm volatile("cp.async.wait_group 0;" ::: "memory");
        else         asm volatile("cp.async.wait_group 1;" ::: "memory");
        __syncthreads();

        __nv_bfloat16* sWh = sbase + cur*P_STAGE;
        __nv_bfloat16* sWl = sWh + 128*LDK;
        __nv_bfloat16* sXh = sWl + 128*LDK;
        __nv_bfloat16* sXl = sXh + 32*LDA;

        #pragma unroll
        for (int kk = 0; kk < 2; kk++) {
            wmma::fragment<wmma::matrix_a, 16, 16, 16, __nv_bfloat16, wmma::row_major> ah[2], al[2];
            #pragma unroll
            for (int mt = 0; mt < 2; mt++) {
                const int o0 = wm*32 + mt*16;
                wmma::load_matrix_sync(ah[mt], &sWh[o0*LDK + kk*16], LDK);
                wmma::load_matrix_sync(al[mt], &sWl[o0*LDK + kk*16], LDK);
            }
            #pragma unroll
            for (int nt = 0; nt < 4; nt++) {
                wmma::fragment<wmma::matrix_b, 16, 16, 16, __nv_bfloat16, wmma::row_major> bh, bl;
                const int c0 = wn*64 + nt*16;
                wmma::load_matrix_sync(bh, &sXh[kk*16*LDA + c0], LDA);
                wmma::load_matrix_sync(bl, &sXl[kk*16*LDA + c0], LDA);
                #pragma unroll
                for (int mt = 0; mt < 2; mt++) {
                    wmma::mma_sync(acc[mt][nt], ah[mt], bh, acc[mt][nt]);
                    wmma::mma_sync(acc[mt][nt], ah[mt], bl, acc[mt][nt]);
                    wmma::mma_sync(acc[mt][nt], al[mt], bh, acc[mt][nt]);
                }
            }
        }

        __syncthreads();
        if (kt < 2) stage_cp(cur, kt + 2);
    }

    // Epilogue: exp, split, store pair + row partial sums
    float* st = stage + w * 16 * 20;
    float rs0 = 0.f, rs1 = 0.f;
    __nv_bfloat16* dh = (m == 0) ? g_Eh : g_Fh;
    __nv_bfloat16* dl = (m == 0) ? g_El : g_Fl;
    #pragma unroll
    for (int mt = 0; mt < 2; mt++)
        #pragma unroll
        for (int nt = 0; nt < 4; nt++) {
            wmma::store_matrix_sync(st, acc[mt][nt], 20, wmma::mem_row_major);
            __syncwarp();
            const int r = lane & 15, c8 = (lane >> 4) * 8;
            const int o = wm*32 + mt*16 + r;
            const int nn = n0 + wn*64 + nt*16 + c8;
            const float* sp = st + r*20 + c8;
            const size_t gb = ((size_t)b * NC + o) * HW + nn;
            float v[8];
            float lsum = 0.f;
            #pragma unroll
            for (int k = 0; k < 8; k++) { v[k] = __expf(sp[k]); lsum += v[k]; }
            if (mt == 0) rs0 += lsum; else rs1 += lsum;
            #pragma unroll
            for (int k = 0; k < 8; k += 2) {
                __nv_bfloat16 h0, l0, h1, l1;
                split_bf16(v[k],   h0, l0);
                split_bf16(v[k+1], h1, l1);
                *(__nv_bfloat162*)&dh[gb + k] = __halves2bfloat162(h0, h1);
                *(__nv_bfloat162*)&dl[gb + k] = __halves2bfloat162(l0, l1);
            }
            __syncwarp();
        }

    {
        const int idx = wn*2 + (lane >> 4), r = lane & 15;
        zsm[(wm*32 + r)*4 + idx]      = rs0;
        zsm[(wm*32 + 16 + r)*4 + idx] = rs1;
        __syncthreads();
        if (tid < 128) {
            float z = zsm[tid*4] + zsm[tid*4+1] + zsm[tid*4+2] + zsm[tid*4+3];
            float* zp = (m == 0) ? g_zBp : g_zVp;
            zp[blockIdx.x*NROW + b*NC + tid] = z;
        }
    }
}

// ---------------------------------------------------------------------------
// Kernel G: M partials: gdp[s][b][i][c] = sum_{n in 512-chunk} E[i,n]*x[c,n]
// block 128i x 128c, warp 32i x 64c, 256 thr, 2 blk/SM. KSPLIT=8 (256 blocks,
// single 0.86 wave; halves gdp traffic). cp.async 2-stage, k-chunk 32, 16 iters.
// ---------------------------------------------------------------------------
#define GD_STAGE (4*128*LDK)
#define GD_SMEM  (2*GD_STAGE*2)

__global__ __launch_bounds__(256, 2) void gd_wmma()
{
    extern __shared__ char smraw[];
    __nv_bfloat16* sbase = (__nv_bfloat16*)smraw;
    const uint32_t sb_u32 = smem_u32(smraw);

    const int tid = threadIdx.x, w = tid >> 5;
    const int s = blockIdx.x, b = blockIdx.y;
    const int kbase = s * 512;
    const int wi = w & 3, wc = w >> 2;

    const int er = tid >> 1, es = (tid & 1) * 2;
    const __nv_bfloat16* Ehp = g_Eh + (size_t)(b*NC + er) * HW;
    const __nv_bfloat16* Elp = g_El + (size_t)(b*NC + er) * HW;
    const __nv_bfloat16* Xhp = g_xh + (size_t)(b*NC + er) * HW;
    const __nv_bfloat16* Xlp = g_xl + (size_t)(b*NC + er) * HW;

    auto stage = [&](int st, int kt) {
        const int kk0 = kbase + kt * 32;
        const uint32_t sb = sb_u32 + st * GD_STAGE * 2;
        #pragma unroll
        for (int q = 0; q < 2; q++) {
            const int sg = es + q;
            cp16(sb + (er*LDK + sg*8)*2,             Ehp + kk0 + sg*8);
            cp16(sb + (128*LDK + er*LDK + sg*8)*2,   Elp + kk0 + sg*8);
            cp16(sb + (2*128*LDK + er*LDK + sg*8)*2, Xhp + kk0 + sg*8);
            cp16(sb + (3*128*LDK + er*LDK + sg*8)*2, Xlp + kk0 + sg*8);
        }
        asm volatile("cp.async.commit_group;");
    };

    stage(0, 0);
    stage(1, 1);

    wmma::fragment<wmma::accumulator, 16, 16, 16, float> acc[2][4];
    #pragma unroll
    for (int mt = 0; mt < 2; mt++)
        #pragma unroll
        for (int nt = 0; nt < 4; nt++)
            wmma::fill_fragment(acc[mt][nt], 0.0f);

    #pragma unroll 4
    for (int kt = 0; kt < 16; kt++) {
        const int cur = kt & 1;
        if (kt == 15) asm volatile("cp.async.wait_group 0;" ::: "memory");
        else          asm volatile("cp.async.wait_group 1;" ::: "memory");
        __syncthreads();

        __nv_bfloat16* sEh = sbase + cur*GD_STAGE;
        __nv_bfloat16* sEl = sEh + 128*LDK;
        __nv_bfloat16* sXh = sEl + 128*LDK;
        __nv_bfloat16* sXl = sXh + 128*LDK;

        #pragma unroll
        for (int kk = 0; kk < 2; kk++) {
            wmma::fragment<wmma::matrix_a, 16, 16, 16, __nv_bfloat16, wmma::row_major> ah[2], al[2];
            #pragma unroll
            for (int mt = 0; mt < 2; mt++) {
                const int i0 = wi*32 + mt*16;
                wmma::load_matrix_sync(ah[mt], &sEh[i0*LDK + kk*16], LDK);
                wmma::load_matrix_sync(al[mt], &sEl[i0*LDK + kk*16], LDK);
            }
            #pragma unroll
            for (int nt = 0; nt < 4; nt++) {
                wmma::fragment<wmma::matrix_b, 16, 16, 16, __nv_bfloat16, wmma::col_major> bh, bl;
                const int c0 = wc*64 + nt*16;
                wmma::load_matrix_sync(bh, &sXh[c0*LDK + kk*16], LDK);
                wmma::load_matrix_sync(bl, &sXl[c0*LDK + kk*16], LDK);
                #pragma unroll
                for (int mt = 0; mt < 2; mt++) {
                    wmma::mma_sync(acc[mt][nt], ah[mt], bh, acc[mt][nt]);
                    wmma::mma_sync(acc[mt][nt], ah[mt], bl, acc[mt][nt]);
                    wmma::mma_sync(acc[mt][nt], al[mt], bh, acc[mt][nt]);
                }
            }
        }

        __syncthreads();
        if (kt < 14) stage(cur, kt + 2);
    }

    float* gp = g_gdp + ((size_t)s * NB + b) * NC * NC;
    #pragma unroll
    for (int mt = 0; mt < 2; mt++)
        #pragma unroll
        for (int nt = 0; nt < 4; nt++)
            wmma::store_matrix_sync(gp + (wi*32 + mt*16) * NC + wc*64 + nt*16,
                                    acc[mt][nt], NC, wmma::mem_row_major);
}

// ---------------------------------------------------------------------------
// Kernel S1: g_gds = sum over splits of gdp (fp32, wide-parallel)
// ---------------------------------------------------------------------------
__global__ __launch_bounds__(256) void gdsum_kernel()
{
    const int idx = blockIdx.x * 256 + threadIdx.x;   // < NB*NC*NC
    float sum = 0.f;
    #pragma unroll
    for (int s = 0; s < KSPLIT; s++)
        sum += g_gdp[(size_t)s * (NB*NC*NC) + idx];
    g_gds[idx] = sum;
}

// ---------------------------------------------------------------------------
// Kernel S2: zfin fused (scales only; gdsum stays separate — R14 lesson).
//   gd'^T[b][j][i] = (sum_c M[i][c]*wA[j][c])*scl[i] + bA[j]*bscl[i]
// Exact fp32 GEMM per batch. grid 32 blocks, 256 threads (16x16), 8jx8i tile.
// ---------------------------------------------------------------------------
#define LDR 132
#define GG_SMEM (2*128*LDR*4 + 2*128*4)

__global__ __launch_bounds__(256, 1) void gdgemm_kernel(
    const float* __restrict__ wA, const float* __restrict__ bA)
{
    extern __shared__ char smraw[];
    float* sM = (float*)smraw;          // [c][i]
    float* sW = sM + 128*LDR;           // [c][j]
    float* sscl  = sW + 128*LDR;        // [128]
    float* sbscl = sscl + 128;          // [128]

    const int b = blockIdx.x, tid = threadIdx.x;
    const int tx = tid & 15, ty = tid >> 4;

    // fused zfin: per-row scales from z partials
    if (tid < 128) {
        const int row = b * NC + tid;
        float zb = 0.f, zv = 0.f;
        #pragma unroll
        for (int nb = 0; nb < 32; nb++) {
            zb += g_zBp[nb*NROW + row];
            zv += g_zVp[nb*NROW + row];
        }
        sscl[tid]  = 1.0f / (zb * (float)HW * zv);
        sbscl[tid] = 1.0f / ((float)HW * zv);
    }

    for (int idx = tid; idx < NC*NC; idx += 256) {
        const int r = idx >> 7, c = idx & 127;
        sM[c*LDR + r] = g_gds[b*NC*NC + idx];
        sW[c*LDR + r] = wA[idx];
    }
    __syncthreads();

    float acc[8][8];
    #pragma unroll
    for (int a = 0; a < 8; a++)
        #pragma unroll
        for (int d = 0; d < 8; d++) acc[a][d] = 0.f;

    for (int c = 0; c < 128; c++) {
        float4 j0 = *(const float4*)&sW[c*LDR + ty*8];
        float4 j1 = *(const float4*)&sW[c*LDR + ty*8 + 4];
        float4 i0 = *(const float4*)&sM[c*LDR + tx*8];
        float4 i1 = *(const float4*)&sM[c*LDR + tx*8 + 4];
        const float jv[8] = {j0.x, j0.y, j0.z, j0.w, j1.x, j1.y, j1.z, j1.w};
        const float iv[8] = {i0.x, i0.y, i0.z, i0.w, i1.x, i1.y, i1.z, i1.w};
        #pragma unroll
        for (int a = 0; a < 8; a++)
            #pragma unroll
            for (int d = 0; d < 8; d++)
                acc[a][d] += jv[a] * iv[d];
    }

    #pragma unroll
    for (int a = 0; a < 8; a++) {
        const int j = ty*8 + a;
        const float bAj = bA[j];
        #pragma unroll
        for (int d = 0; d < 8; d += 2) {
            const int i = tx*8 + d;
            const float v0 = acc[a][d]   * sscl[i]   + bAj * sbscl[i];
            const float v1 = acc[a][d+1] * sscl[i+1] + bAj * sbscl[i+1];
            __nv_bfloat16 h0, l0, h1, l1;
            split_bf16(v0, h0, l0);
            split_bf16(v1, h1, l1);
            const size_t t = (size_t)b*NC*NC + (size_t)j*NC + i;
            *(__nv_bfloat162*)&g_gTh[t] = __halves2bfloat162(h0, h1);
            *(__nv_bfloat162*)&g_gTl[t] = __halves2bfloat162(l0, l1);
        }
    }
}

// ---------------------------------------------------------------------------
// Kernel O: out[b,j,n] = sum_i F[i,n]*gd'[i,j]  (3-term bf16 GEMM, K=128)
// cp.async 2-stage, k-chunk 32 (4 iters). grid (HW/128, NB), 256 thr, 2 blk/SM.
// stage (elems): [Gh 128*LDK][Gl 128*LDK][Fh 32*LDA][Fl 32*LDA]
// ---------------------------------------------------------------------------
#define O_STAGE (2*128*LDK + 2*32*LDA)
#define OUT_SMEM (2*O_STAGE*2)

__global__ __launch_bounds__(256, 2) void out_wmma(float* __restrict__ out)
{
    extern __shared__ char smraw[];
    __nv_bfloat16* sbase = (__nv_bfloat16*)smraw;
    const uint32_t sb_u32 = smem_u32(smraw);

    const int tid = threadIdx.x, w = tid >> 5;
    const int b = blockIdx.y, n0 = blockIdx.x * 128;
    const int wm = w & 3, wn = w >> 2;

    // staging maps (hl = tid>>7)
    const int hl = tid >> 7, gr = tid & 127;
    const __nv_bfloat16* gsrc = (hl ? g_gTl : g_gTh) + (size_t)(b*NC + gr) * NC;
    const int fq0 = (tid & 127) * 4;
    const __nv_bfloat16* fsrc = (hl ? g_Fl : g_Fh);

    auto stage = [&](int st, int kt) {
        const uint32_t sb = sb_u32 + st * O_STAGE * 2;
        const uint32_t gdst = sb + (hl*128*LDK + gr*LDK)*2;
        #pragma unroll
        for (int sg = 0; sg < 4; sg++)
            cp16(gdst + sg*16, gsrc + kt*32 + sg*8);
        const uint32_t fdst = sb + (2*128*LDK + hl*32*LDA)*2;
        #pragma unroll
        for (int q = 0; q < 4; q++) {
            const int idx = fq0 + q, row = idx >> 4, sg = idx & 15;
            cp16(fdst + (row*LDA + sg*8)*2,
                 fsrc + (size_t)(b*NC + kt*32 + row)*HW + n0 + sg*8);
        }
        asm volatile("cp.async.commit_group;");
    };

    stage(0, 0);
    stage(1, 1);

    wmma::fragment<wmma::accumulator, 16, 16, 16, float> acc[2][4];
    #pragma unroll
    for (int mt = 0; mt < 2; mt++)
        #pragma unroll
        for (int nt = 0; nt < 4; nt++)
            wmma::fill_fragment(acc[mt][nt], 0.0f);

    #pragma unroll
    for (int kt = 0; kt < 4; kt++) {
        const int cur = kt & 1;
        if (kt == 3) asm volatile("cp.async.wait_group 0;" ::: "memory");
        else         asm volatile("cp.async.wait_group 1;" ::: "memory");
        __syncthreads();

        __nv_bfloat16* bGh = sbase + cur*O_STAGE;
        __nv_bfloat16* bGl = bGh + 128*LDK;
        __nv_bfloat16* bFh = bGl + 128*LDK;
        __nv_bfloat16* bFl = bFh + 32*LDA;

        #pragma unroll
        for (int kk = 0; kk < 2; kk++) {
            wmma::fragment<wmma::matrix_a, 16, 16, 16, __nv_bfloat16, wmma::row_major> ah[2], al[2];
            #pragma unroll
            for (int mt = 0; mt < 2; mt++) {
                const int j0 = wm*32 + mt*16;
                wmma::load_matrix_sync(ah[mt], &bGh[j0*LDK + kk*16], LDK);
                wmma::load_matrix_sync(al[mt], &bGl[j0*LDK + kk*16], LDK);
            }
            #pragma unroll
            for (int nt = 0; nt < 4; nt++) {
                wmma::fragment<wmma::matrix_b, 16, 16, 16, __nv_bfloat16, wmma::row_major> bh, bl;
                const int c0 = wn*64 + nt*16;
                wmma::load_matrix_sync(bh, &bFh[kk*16*LDA + c0], LDA);
                wmma::load_matrix_sync(bl, &bFl[kk*16*LDA + c0], LDA);
                #pragma unroll
                for (int mt = 0; mt < 2; mt++) {
                    wmma::mma_sync(acc[mt][nt], ah[mt], bh, acc[mt][nt]);
                    wmma::mma_sync(acc[mt][nt], ah[mt], bl, acc[mt][nt]);
                    wmma::mma_sync(acc[mt][nt], al[mt], bh, acc[mt][nt]);
                }
            }
        }

        __syncthreads();
        if (kt < 2) stage(cur, kt + 2);
    }

    #pragma unroll
    for (int mt = 0; mt < 2; mt++)
        #pragma unroll
        for (int nt = 0; nt < 4; nt++) {
            float* gp = out + ((size_t)b * NC + wm*32 + mt*16) * HW + n0 + wn*64 + nt*16;
            wmma::store_matrix_sync(gp, acc[mt][nt], HW, wmma::mem_row_major);
        }
}

// ---------------------------------------------------------------------------
extern "C" void kernel_launch(void* const* d_in, const int* in_sizes, int n_in,
                              void* d_out, int out_size)
{
    const float* x  = (const float*)d_in[0];
    const float* wA = (const float*)d_in[1];
    const float* bA = (const float*)d_in[2];
    const float* wB = (const float*)d_in[3];
    const float* bB = (const float*)d_in[4];  // unused: softmax shift-invariant
    const float* wV = (const float*)d_in[5];
    const float* bV = (const float*)d_in[6];  // unused: softmax shift-invariant
    (void)bB; (void)bV;
    float* out = (float*)d_out;

    cudaFuncSetAttribute(proj_wmma,    cudaFuncAttributeMaxDynamicSharedMemorySize, PROJ_SMEM);
    cudaFuncSetAttribute(gd_wmma,      cudaFuncAttributeMaxDynamicSharedMemorySize, GD_SMEM);
    cudaFuncSetAttribute(gdgemm_kernel,cudaFuncAttributeMaxDynamicSharedMemorySize, GG_SMEM);
    cudaFuncSetAttribute(out_wmma,     cudaFuncAttributeMaxDynamicSharedMemorySize, OUT_SMEM);

    wconv_kernel <<<2, 256>>>(wB, wV);
    xconv_kernel <<<(NB*NC*HW)/1024, 256>>>(x);
    proj_wmma    <<<dim3(HW/128, NB, 2), 256, PROJ_SMEM>>>();
    gd_wmma      <<<dim3(KSPLIT, NB), 256, GD_SMEM>>>();
    gdsum_kernel <<<(NB*NC*NC)/256, 256>>>();
    gdgemm_kernel<<<NB, 256, GG_SMEM>>>(wA, bA);
    out_wmma     <<<dim3(HW/128, NB), 256, OUT_SMEM>>>(out);
}